// round 11
// baseline (speedup 1.0000x reference)
#include <cuda_runtime.h>
#include <math.h>

#define NN 50000
#define EE 400000
#define GG 64
#define EPSBN 1e-5f
#define APAD 20    // A tile row stride (floats)
#define BPAD 136   // B tile row stride (floats)
#define SPAD 132   // staging tile row stride

// weight-split buffer offsets (floats)
#define TWI   32768            // Wi 256x128
#define TW1   41344            // per-layer msg_W1 323x128
#define OFF_W1  (TWI)
#define OFF_NW  (TWI + 3 * TW1)             // 156800
#define OFF_W2  (OFF_NW + 3 * 16384)        // 205952
#define WTOT    (OFF_W2 + 3 * 16384)        // 255104

// ---------------- scratch ------------------------------------------------------
__device__ float g_h[NN * 128];
__device__ float g_Ab[NN * 128];
__device__ float g_Bb[NN * 128];
__device__ float g_U[NN * 128];
__device__ float g_S[NN * 128];
__device__ float g_Whi[WTOT];
__device__ float g_Wlo[WTOT];
__device__ int   g_src[EE];
__device__ int   g_dst[EE];
__device__ int   g_batch[NN];
__device__ float g_deg[NN];
__device__ float g_P[GG * 128];
__device__ float g_cnt[GG];
__device__ int   g_e64;
__device__ int   g_b64;

// ---------------- dtype detection ----------------------------------------------
__global__ void detect_kernel(const void* ei, const void* bt, int N, int E) {
    __shared__ int s_e, s_b;
    int t = threadIdx.x;
    if (t == 0) { s_e = 1; s_b = 1; }
    __syncthreads();
    const long long* p = (const long long*)ei;
    long long v = p[t];
    if (v < 0 || v >= (long long)N) s_e = 0;
    int base = N / 2 - 256; if (base < 0) base = 0;
    const long long* q = (const long long*)bt;
    long long w = q[base + t];
    if (w < 0 || w >= (long long)GG) s_b = 0;
    __syncthreads();
    if (t == 0) { g_e64 = s_e; g_b64 = s_b; }
}

__global__ void convert_kernel(const void* ei, const void* bt, int N, int E) {
    int i = blockIdx.x * blockDim.x + threadIdx.x;
    int e64 = g_e64, b64 = g_b64;
    if (i < E) {
        if (e64) {
            const long long* p = (const long long*)ei;
            g_src[i] = (int)p[i];
            g_dst[i] = (int)p[E + i];
        } else {
            const int* p = (const int*)ei;
            g_src[i] = p[i];
            g_dst[i] = p[E + i];
        }
    }
    if (i < N) {
        if (b64) g_batch[i] = (int)((const long long*)bt)[i];
        else     g_batch[i] = ((const int*)bt)[i];
        g_deg[i] = 1.0f;   // self loop
    }
}

__global__ void deg_kernel(int E) {
    int i = blockIdx.x * blockDim.x + threadIdx.x;
    if (i < E) atomicAdd(&g_deg[g_dst[i]], 1.0f);
}

// ---------------- tf32 helpers --------------------------------------------------
__device__ __forceinline__ void tf32_split_f(float v, float& hi, float& lo) {
    unsigned u;
    asm("cvt.rna.tf32.f32 %0, %1;" : "=r"(u) : "f"(v));
    hi = __uint_as_float(u);
    float l = v - hi;
    asm("cvt.rna.tf32.f32 %0, %1;" : "=r"(u) : "f"(l));
    lo = __uint_as_float(u);
}

// ---------------- weight split prologue -----------------------------------------
__global__ void split_weights(const float* __restrict__ Wi,
                              const float* __restrict__ msg_W1,
                              const float* __restrict__ node_W,
                              const float* __restrict__ msg_W2)
{
    int i = blockIdx.x * blockDim.x + threadIdx.x;
    if (i >= WTOT) return;
    float v;
    if (i < TWI)            v = Wi[i];
    else if (i < OFF_NW)    v = msg_W1[i - OFF_W1];
    else if (i < OFF_W2)    v = node_W[i - OFF_NW];
    else                    v = msg_W2[i - OFF_W2];
    float hi, lo;
    tf32_split_f(v, hi, lo);
    g_Whi[i] = hi;
    g_Wlo[i] = lo;
}

#define MMA_TF32(d, a, b)                                              \
    asm volatile("mma.sync.aligned.m16n8k8.row.col.f32.tf32.tf32.f32 " \
        "{%0,%1,%2,%3}, {%4,%5,%6,%7}, {%8,%9}, {%0,%1,%2,%3};"        \
        : "+f"((d)[0]), "+f"((d)[1]), "+f"((d)[2]), "+f"((d)[3])       \
        : "r"((a)[0]), "r"((a)[1]), "r"((a)[2]), "r"((a)[3]),          \
          "r"((b)[0]), "r"((b)[1]))

// fragment loads (pre-split tiles) + 3xTF32 MMA, M64xN128 tiling
#define MMA_SLAB(sAhi, sAlo, sBhi, sBlo, acc)                                   \
    _Pragma("unroll")                                                           \
    for (int kk = 0; kk < 16; kk += 8) {                                        \
        unsigned ahi[2][4], alo[2][4], bhi[4][2], blo[4][2];                    \
        _Pragma("unroll")                                                       \
        for (int mt = 0; mt < 2; mt++) {                                        \
            int base = (wm + mt * 16 + g) * APAD + kk + tg;                     \
            ahi[mt][0] = __float_as_uint(sAhi[base]);                           \
            ahi[mt][1] = __float_as_uint(sAhi[base + 8 * APAD]);                \
            ahi[mt][2] = __float_as_uint(sAhi[base + 4]);                       \
            ahi[mt][3] = __float_as_uint(sAhi[base + 8 * APAD + 4]);            \
            alo[mt][0] = __float_as_uint(sAlo[base]);                           \
            alo[mt][1] = __float_as_uint(sAlo[base + 8 * APAD]);                \
            alo[mt][2] = __float_as_uint(sAlo[base + 4]);                       \
            alo[mt][3] = __float_as_uint(sAlo[base + 8 * APAD + 4]);            \
        }                                                                       \
        _Pragma("unroll")                                                       \
        for (int nt = 0; nt < 4; nt++) {                                        \
            int n = wn + nt * 8 + g;                                            \
            bhi[nt][0] = __float_as_uint(sBhi[(kk + tg) * BPAD + n]);           \
            bhi[nt][1] = __float_as_uint(sBhi[(kk + tg + 4) * BPAD + n]);       \
            blo[nt][0] = __float_as_uint(sBlo[(kk + tg) * BPAD + n]);           \
            blo[nt][1] = __float_as_uint(sBlo[(kk + tg + 4) * BPAD + n]);       \
        }                                                                       \
        _Pragma("unroll")                                                       \
        for (int mt = 0; mt < 2; mt++)                                          \
            _Pragma("unroll")                                                   \
            for (int nt = 0; nt < 4; nt++) {                                    \
                MMA_TF32(acc[mt][nt], ahi[mt], bhi[nt]);                        \
                MMA_TF32(acc[mt][nt], ahi[mt], blo[nt]);                        \
                MMA_TF32(acc[mt][nt], alo[mt], bhi[nt]);                        \
            }                                                                   \
    }

// split a float4 into hi/lo float4s
__device__ __forceinline__ void split4(const float4& v, float4& hi, float4& lo) {
    tf32_split_f(v.x, hi.x, lo.x);
    tf32_split_f(v.y, hi.y, lo.y);
    tf32_split_f(v.z, hi.z, lo.z);
    tf32_split_f(v.w, hi.w, lo.w);
}

// ---------------- generic GEMM (init): C[M,128] = A[M,K]@W + bias, M-tile 64 ---
__global__ __launch_bounds__(256) void gemm64(
    const float* __restrict__ Ap, int lda,
    const float* __restrict__ Whi, const float* __restrict__ Wlo,
    const float* __restrict__ bias,
    float* __restrict__ Cp, int M, int K)
{
    __shared__ __align__(16) float sAhi[64 * APAD], sAlo[64 * APAD];
    __shared__ __align__(16) float sBhi[16 * BPAD], sBlo[16 * BPAD];
    int t = threadIdx.x, lane = t & 31, w = t >> 5;
    int wm = (w & 1) * 32, wn = (w >> 1) * 32;
    int g = lane >> 2, tg = lane & 3;
    int m0 = blockIdx.x * 64;
    int arow = t >> 2, akq = t & 3;
    int bkr = t >> 4, bn4 = (t & 15) * 8;
    int gm = m0 + arow;
    float acc[2][4][4];
#pragma unroll
    for (int a = 0; a < 2; a++)
#pragma unroll
        for (int b = 0; b < 4; b++)
#pragma unroll
            for (int c = 0; c < 4; c++) acc[a][b][c] = 0.f;

    float4 va = make_float4(0.f, 0.f, 0.f, 0.f);
    if (gm < M) va = *(const float4*)(Ap + (size_t)gm * lda + akq * 4);
    float4 vh0 = *(const float4*)(Whi + (size_t)bkr * 128 + bn4);
    float4 vh1 = *(const float4*)(Whi + (size_t)bkr * 128 + bn4 + 4);
    float4 vl0 = *(const float4*)(Wlo + (size_t)bkr * 128 + bn4);
    float4 vl1 = *(const float4*)(Wlo + (size_t)bkr * 128 + bn4 + 4);

    for (int k0 = 0; k0 < K; k0 += 16) {
        float4 ahi4, alo4;
        split4(va, ahi4, alo4);
        *(float4*)&sAhi[arow * APAD + akq * 4] = ahi4;
        *(float4*)&sAlo[arow * APAD + akq * 4] = alo4;
        *(float4*)&sBhi[bkr * BPAD + bn4]      = vh0;
        *(float4*)&sBhi[bkr * BPAD + bn4 + 4]  = vh1;
        *(float4*)&sBlo[bkr * BPAD + bn4]      = vl0;
        *(float4*)&sBlo[bkr * BPAD + bn4 + 4]  = vl1;
        __syncthreads();
        int kn = k0 + 16;
        if (kn < K) {
            va = make_float4(0.f, 0.f, 0.f, 0.f);
            if (gm < M) va = *(const float4*)(Ap + (size_t)gm * lda + kn + akq * 4);
            vh0 = *(const float4*)(Whi + (size_t)(kn + bkr) * 128 + bn4);
            vh1 = *(const float4*)(Whi + (size_t)(kn + bkr) * 128 + bn4 + 4);
            vl0 = *(const float4*)(Wlo + (size_t)(kn + bkr) * 128 + bn4);
            vl1 = *(const float4*)(Wlo + (size_t)(kn + bkr) * 128 + bn4 + 4);
        }
        MMA_SLAB(sAhi, sAlo, sBhi, sBlo, acc)
        __syncthreads();
    }
#pragma unroll
    for (int mt = 0; mt < 2; mt++) {
        int r0 = m0 + wm + mt * 16 + g;
#pragma unroll
        for (int nt = 0; nt < 4; nt++) {
            int c = wn + nt * 8 + 2 * tg;
            float b0 = bias ? bias[c] : 0.f;
            float b1 = bias ? bias[c + 1] : 0.f;
            if (r0 < M) {
                Cp[(size_t)r0 * 128 + c]     = acc[mt][nt][0] + b0;
                Cp[(size_t)r0 * 128 + c + 1] = acc[mt][nt][1] + b1;
            }
            if (r0 + 8 < M) {
                Cp[(size_t)(r0 + 8) * 128 + c]     = acc[mt][nt][2] + b0;
                Cp[(size_t)(r0 + 8) * 128 + c + 1] = acc[mt][nt][3] + b1;
            }
        }
    }
}

// ------- fused node GEMMs: y=0: A=h@W1a, y=1: B=h@W1b, y=2: U=h@nodeW+node_b ---
__global__ __launch_bounds__(256) void gemm_h3(
    const float* __restrict__ WaHi, const float* __restrict__ WaLo,
    const float* __restrict__ WbHi, const float* __restrict__ WbLo,
    const float* __restrict__ WnHi, const float* __restrict__ WnLo,
    const float* __restrict__ nodeB, int M)
{
    __shared__ __align__(16) float sAhi[64 * APAD], sAlo[64 * APAD];
    __shared__ __align__(16) float sBhi[16 * BPAD], sBlo[16 * BPAD];
    int y = blockIdx.y;
    const float* Whi = (y == 0) ? WaHi : ((y == 1) ? WbHi : WnHi);
    const float* Wlo = (y == 0) ? WaLo : ((y == 1) ? WbLo : WnLo);
    float* Cp = (y == 0) ? g_Ab : ((y == 1) ? g_Bb : g_U);
    const float* bias = (y == 2) ? nodeB : 0;

    int t = threadIdx.x, lane = t & 31, w = t >> 5;
    int wm = (w & 1) * 32, wn = (w >> 1) * 32;
    int g = lane >> 2, tg = lane & 3;
    int m0 = blockIdx.x * 64;
    int arow = t >> 2, akq = t & 3;
    int bkr = t >> 4, bn4 = (t & 15) * 8;
    int gm = m0 + arow;
    float acc[2][4][4];
#pragma unroll
    for (int a = 0; a < 2; a++)
#pragma unroll
        for (int b = 0; b < 4; b++)
#pragma unroll
            for (int c = 0; c < 4; c++) acc[a][b][c] = 0.f;

    float4 va = make_float4(0.f, 0.f, 0.f, 0.f);
    if (gm < M) va = *(const float4*)(g_h + (size_t)gm * 128 + akq * 4);
    float4 vh0 = *(const float4*)(Whi + (size_t)bkr * 128 + bn4);
    float4 vh1 = *(const float4*)(Whi + (size_t)bkr * 128 + bn4 + 4);
    float4 vl0 = *(const float4*)(Wlo + (size_t)bkr * 128 + bn4);
    float4 vl1 = *(const float4*)(Wlo + (size_t)bkr * 128 + bn4 + 4);

    for (int k0 = 0; k0 < 128; k0 += 16) {
        float4 ahi4, alo4;
        split4(va, ahi4, alo4);
        *(float4*)&sAhi[arow * APAD + akq * 4] = ahi4;
        *(float4*)&sAlo[arow * APAD + akq * 4] = alo4;
        *(float4*)&sBhi[bkr * BPAD + bn4]      = vh0;
        *(float4*)&sBhi[bkr * BPAD + bn4 + 4]  = vh1;
        *(float4*)&sBlo[bkr * BPAD + bn4]      = vl0;
        *(float4*)&sBlo[bkr * BPAD + bn4 + 4]  = vl1;
        __syncthreads();
        int kn = k0 + 16;
        if (kn < 128) {
            va = make_float4(0.f, 0.f, 0.f, 0.f);
            if (gm < M) va = *(const float4*)(g_h + (size_t)gm * 128 + kn + akq * 4);
            vh0 = *(const float4*)(Whi + (size_t)(kn + bkr) * 128 + bn4);
            vh1 = *(const float4*)(Whi + (size_t)(kn + bkr) * 128 + bn4 + 4);
            vl0 = *(const float4*)(Wlo + (size_t)(kn + bkr) * 128 + bn4);
            vl1 = *(const float4*)(Wlo + (size_t)(kn + bkr) * 128 + bn4 + 4);
        }
        MMA_SLAB(sAhi, sAlo, sBhi, sBlo, acc)
        __syncthreads();
    }
#pragma unroll
    for (int mt = 0; mt < 2; mt++) {
        int r0 = m0 + wm + mt * 16 + g;
#pragma unroll
        for (int nt = 0; nt < 4; nt++) {
            int c = wn + nt * 8 + 2 * tg;
            float b0 = bias ? bias[c] : 0.f;
            float b1 = bias ? bias[c + 1] : 0.f;
            if (r0 < M) {
                Cp[(size_t)r0 * 128 + c]     = acc[mt][nt][0] + b0;
                Cp[(size_t)r0 * 128 + c + 1] = acc[mt][nt][1] + b1;
            }
            if (r0 + 8 < M) {
                Cp[(size_t)(r0 + 8) * 128 + c]     = acc[mt][nt][2] + b0;
                Cp[(size_t)(r0 + 8) * 128 + c + 1] = acc[mt][nt][3] + b1;
            }
        }
    }
}

// ------- fused edge pass: GEMM(ea@W1c) + gather A/B/relpos + BN/ReLU + scatter --
__global__ __launch_bounds__(256) void edge_fused(
    const float* __restrict__ ea, const float* __restrict__ pos,
    const float* __restrict__ W1,
    const float* __restrict__ WcHi, const float* __restrict__ WcLo,
    const float* __restrict__ gn, const float* __restrict__ be,
    const float* __restrict__ b1, int E)
{
    __shared__ __align__(16) float sAhi[64 * APAD], sAlo[64 * APAD];
    __shared__ __align__(16) float sBhi[16 * BPAD], sBlo[16 * BPAD];
    __shared__ __align__(16) float stage[32 * SPAD];
    __shared__ __align__(16) float w1d[3 * 128];
    __shared__ __align__(16) float sc[128], sh[128];
    __shared__ float srp[64 * 3];
    __shared__ int   sdst[64], ssrc[64];

    int t = threadIdx.x, lane = t & 31, w = t >> 5;
    int wm = (w & 1) * 32, wn = (w >> 1) * 32;
    int g = lane >> 2, tg = lane & 3;
    int m0 = blockIdx.x * 64;

    if (t < 128) {
        float s = gn[t] * rsqrtf(1.0f + EPSBN);
        sc[t] = s;
        sh[t] = fmaf(b1[t], s, be[t]);
        w1d[t]       = W1[320 * 128 + t];
        w1d[128 + t] = W1[321 * 128 + t];
        w1d[256 + t] = W1[322 * 128 + t];
    }
    if (t < 64) {
        int e = m0 + t;
        int s = 0, d = 0;
        float r0 = 0.f, r1 = 0.f, r2 = 0.f;
        if (e < E) {
            s = g_src[e]; d = g_dst[e];
            r0 = pos[d * 3 + 0] - pos[s * 3 + 0];
            r1 = pos[d * 3 + 1] - pos[s * 3 + 1];
            r2 = pos[d * 3 + 2] - pos[s * 3 + 2];
        }
        ssrc[t] = s; sdst[t] = d;
        srp[t * 3 + 0] = r0; srp[t * 3 + 1] = r1; srp[t * 3 + 2] = r2;
    }

    int arow = t >> 2, akq = t & 3;
    int bkr = t >> 4, bn4 = (t & 15) * 8;
    int ge = m0 + arow;
    float acc[2][4][4];
#pragma unroll
    for (int a = 0; a < 2; a++)
#pragma unroll
        for (int b = 0; b < 4; b++)
#pragma unroll
            for (int c = 0; c < 4; c++) acc[a][b][c] = 0.f;

    float4 va = make_float4(0.f, 0.f, 0.f, 0.f);
    if (ge < E) va = *(const float4*)(ea + (size_t)ge * 64 + akq * 4);
    float4 vh0 = *(const float4*)(WcHi + (size_t)bkr * 128 + bn4);
    float4 vh1 = *(const float4*)(WcHi + (size_t)bkr * 128 + bn4 + 4);
    float4 vl0 = *(const float4*)(WcLo + (size_t)bkr * 128 + bn4);
    float4 vl1 = *(const float4*)(WcLo + (size_t)bkr * 128 + bn4 + 4);

    for (int k0 = 0; k0 < 64; k0 += 16) {
        float4 ahi4, alo4;
        split4(va, ahi4, alo4);
        *(float4*)&sAhi[arow * APAD + akq * 4] = ahi4;
        *(float4*)&sAlo[arow * APAD + akq * 4] = alo4;
        *(float4*)&sBhi[bkr * BPAD + bn4]      = vh0;
        *(float4*)&sBhi[bkr * BPAD + bn4 + 4]  = vh1;
        *(float4*)&sBlo[bkr * BPAD + bn4]      = vl0;
        *(float4*)&sBlo[bkr * BPAD + bn4 + 4]  = vl1;
        __syncthreads();
        int kn = k0 + 16;
        if (kn < 64) {
            va = make_float4(0.f, 0.f, 0.f, 0.f);
            if (ge < E) va = *(const float4*)(ea + (size_t)ge * 64 + kn + akq * 4);
            vh0 = *(const float4*)(WcHi + (size_t)(kn + bkr) * 128 + bn4);
            vh1 = *(const float4*)(WcHi + (size_t)(kn + bkr) * 128 + bn4 + 4);
            vl0 = *(const float4*)(WcLo + (size_t)(kn + bkr) * 128 + bn4);
            vl1 = *(const float4*)(WcLo + (size_t)(kn + bkr) * 128 + bn4 + 4);
        }
        MMA_SLAB(sAhi, sAlo, sBhi, sBlo, acc)
        __syncthreads();
    }

    // two staging passes (32 edges each); warps with (w&1)==p own rows of pass p
#pragma unroll
    for (int p = 0; p < 2; p++) {
        if ((w & 1) == p) {
#pragma unroll
            for (int mt = 0; mt < 2; mt++)
#pragma unroll
                for (int nt = 0; nt < 4; nt++)
#pragma unroll
                    for (int half = 0; half < 2; half++) {
                        int el = mt * 16 + g + half * 8;  // 0..31
                        int c = wn + nt * 8 + 2 * tg;
                        stage[el * SPAD + c]     = acc[mt][nt][half * 2 + 0];
                        stage[el * SPAD + c + 1] = acc[mt][nt][half * 2 + 1];
                    }
        }
        __syncthreads();
        // scatter: each warp handles 4 edges of this pass
        int j = lane * 4;
        float4 scv = *(const float4*)&sc[j];
        float4 shv = *(const float4*)&sh[j];
        float4 w0 = *(const float4*)&w1d[j];
        float4 w1v = *(const float4*)&w1d[128 + j];
        float4 w2 = *(const float4*)&w1d[256 + j];
#pragma unroll
        for (int i = 0; i < 4; i++) {
            int el = w * 4 + i;                 // 0..31
            int eg = m0 + p * 32 + el;
            if (eg < E) {
                int d = sdst[p * 32 + el], s2 = ssrc[p * 32 + el];
                float rp0 = srp[(p * 32 + el) * 3 + 0];
                float rp1 = srp[(p * 32 + el) * 3 + 1];
                float rp2 = srp[(p * 32 + el) * 3 + 2];
                float4 cv = *(const float4*)&stage[el * SPAD + j];
                float4 av = *(const float4*)&g_Ab[(size_t)d * 128 + j];
                float4 bv = *(const float4*)&g_Bb[(size_t)s2 * 128 + j];
                float m0v = cv.x + av.x + bv.x + rp0 * w0.x + rp1 * w1v.x + rp2 * w2.x;
                float m1v = cv.y + av.y + bv.y + rp0 * w0.y + rp1 * w1v.y + rp2 * w2.y;
                float m2v = cv.z + av.z + bv.z + rp0 * w0.z + rp1 * w1v.z + rp2 * w2.z;
                float m3v = cv.w + av.w + bv.w + rp0 * w0.w + rp1 * w1v.w + rp2 * w2.w;
                float r0 = fmaxf(fmaf(m0v, scv.x, shv.x), 0.f);
                float r1 = fmaxf(fmaf(m1v, scv.y, shv.y), 0.f);
                float r2 = fmaxf(fmaf(m2v, scv.z, shv.z), 0.f);
                float r3 = fmaxf(fmaf(m3v, scv.w, shv.w), 0.f);
                float* pS = &g_S[(size_t)d * 128 + j];
                asm volatile("red.global.add.v4.f32 [%0], {%1, %2, %3, %4};"
                             :: "l"(pS), "f"(r0), "f"(r1), "f"(r2), "f"(r3) : "memory");
            }
        }
        __syncthreads();
    }
}

// ------- node update: h += relu( U + (S + selfmsg)@W2 + deg*b2 ) ---------------
__global__ __launch_bounds__(256) void node1(
    const float* __restrict__ W2Hi, const float* __restrict__ W2Lo,
    const float* __restrict__ b2,
    const float* __restrict__ gn, const float* __restrict__ be,
    const float* __restrict__ b1, int M)
{
    __shared__ __align__(16) float sAhi[64 * APAD], sAlo[64 * APAD];
    __shared__ __align__(16) float sBhi[16 * BPAD], sBlo[16 * BPAD];
    __shared__ float sc[128], sh[128], b2s[128];
    int t = threadIdx.x, lane = t & 31, w = t >> 5;
    if (t < 128) {
        float s = gn[t] * rsqrtf(1.0f + EPSBN);
        sc[t] = s;
        sh[t] = fmaf(b1[t], s, be[t]);
        b2s[t] = b2[t];
    }
    __syncthreads();
    int wm = (w & 1) * 32, wn = (w >> 1) * 32;
    int g = lane >> 2, tg = lane & 3;
    int m0 = blockIdx.x * 64;
    int arow = t >> 2, akq = t & 3;
    int bkr = t >> 4, bn4 = (t & 15) * 8;
    int gm = m0 + arow;
    float acc[2][4][4];
#pragma unroll
    for (int a = 0; a < 2; a++)
#pragma unroll
        for (int b = 0; b < 4; b++)
#pragma unroll
            for (int c = 0; c < 4; c++) acc[a][b][c] = 0.f;

    float4 pv_s = make_float4(0.f, 0.f, 0.f, 0.f);
    float4 pv_a = pv_s, pv_b = pv_s;
    if (gm < M) {
        pv_s = *(const float4*)(g_S  + (size_t)gm * 128 + akq * 4);
        pv_a = *(const float4*)(g_Ab + (size_t)gm * 128 + akq * 4);
        pv_b = *(const float4*)(g_Bb + (size_t)gm * 128 + akq * 4);
    }
    float4 vh0 = *(const float4*)(W2Hi + (size_t)bkr * 128 + bn4);
    float4 vh1 = *(const float4*)(W2Hi + (size_t)bkr * 128 + bn4 + 4);
    float4 vl0 = *(const float4*)(W2Lo + (size_t)bkr * 128 + bn4);
    float4 vl1 = *(const float4*)(W2Lo + (size_t)bkr * 128 + bn4 + 4);

    for (int k0 = 0; k0 < 128; k0 += 16) {
        // build A values: S + relu(bn(A+B)) (self-loop message), split, store
        {
            float4 out;
            float* sp = (float*)&pv_s; float* ap = (float*)&pv_a;
            float* bp = (float*)&pv_b; float* op = (float*)&out;
#pragma unroll
            for (int j = 0; j < 4; j++) {
                int k = k0 + akq * 4 + j;
                float r = fmaxf(fmaf(ap[j] + bp[j], sc[k], sh[k]), 0.f);
                op[j] = sp[j] + r;
            }
            float4 ahi4, alo4;
            split4(out, ahi4, alo4);
            *(float4*)&sAhi[arow * APAD + akq * 4] = ahi4;
            *(float4*)&sAlo[arow * APAD + akq * 4] = alo4;
        }
        *(float4*)&sBhi[bkr * BPAD + bn4]     = vh0;
        *(float4*)&sBhi[bkr * BPAD + bn4 + 4] = vh1;
        *(float4*)&sBlo[bkr * BPAD + bn4]     = vl0;
        *(float4*)&sBlo[bkr * BPAD + bn4 + 4] = vl1;
        __syncthreads();
        int kn = k0 + 16;
        if (kn < 128) {
            pv_s = make_float4(0.f, 0.f, 0.f, 0.f);
            pv_a = pv_s; pv_b = pv_s;
            if (gm < M) {
                pv_s = *(const float4*)(g_S  + (size_t)gm * 128 + kn + akq * 4);
                pv_a = *(const float4*)(g_Ab + (size_t)gm * 128 + kn + akq * 4);
                pv_b = *(const float4*)(g_Bb + (size_t)gm * 128 + kn + akq * 4);
            }
            vh0 = *(const float4*)(W2Hi + (size_t)(kn + bkr) * 128 + bn4);
            vh1 = *(const float4*)(W2Hi + (size_t)(kn + bkr) * 128 + bn4 + 4);
            vl0 = *(const float4*)(W2Lo + (size_t)(kn + bkr) * 128 + bn4);
            vl1 = *(const float4*)(W2Lo + (size_t)(kn + bkr) * 128 + bn4 + 4);
        }
        MMA_SLAB(sAhi, sAlo, sBhi, sBlo, acc)
        __syncthreads();
    }
#pragma unroll
    for (int mt = 0; mt < 2; mt++) {
        int r0 = m0 + wm + mt * 16 + g;
#pragma unroll
        for (int nt = 0; nt < 4; nt++) {
            int c = wn + nt * 8 + 2 * tg;
#pragma unroll
            for (int half = 0; half < 2; half++) {
                int rr = r0 + half * 8;
                if (rr < M) {
                    float dg = g_deg[rr];
                    float u0 = g_U[(size_t)rr * 128 + c];
                    float u1 = g_U[(size_t)rr * 128 + c + 1];
                    float v0 = acc[mt][nt][half * 2 + 0] + u0 + dg * b2s[c];
                    float v1 = acc[mt][nt][half * 2 + 1] + u1 + dg * b2s[c + 1];
                    g_h[(size_t)rr * 128 + c]     += fmaxf(v0, 0.f);
                    g_h[(size_t)rr * 128 + c + 1] += fmaxf(v1, 0.f);
                }
            }
        }
    }
}

// ---------------- pooling + output MLP ------------------------------------------
__global__ void pool_kernel(int N) {
    int w = (blockIdx.x * blockDim.x + threadIdx.x) >> 5;
    int lane = threadIdx.x & 31;
    if (w >= N) return;
    int gph = g_batch[w];
    int j = lane * 4;
    float4 v = *(const float4*)&g_h[(size_t)w * 128 + j];
    float* p = &g_P[(size_t)gph * 128 + j];
    asm volatile("red.global.add.v4.f32 [%0], {%1, %2, %3, %4};"
                 :: "l"(p), "f"(v.x), "f"(v.y), "f"(v.z), "f"(v.w) : "memory");
    if (lane == 0) atomicAdd(&g_cnt[gph], 1.0f);
}

__global__ void head_kernel(
    const float* __restrict__ W1, const float* __restrict__ b1,
    const float* __restrict__ gn, const float* __restrict__ be,
    const float* __restrict__ W2, const float* __restrict__ b2,
    float* __restrict__ out)
{
    __shared__ float pl[128], o1[128];
    int gph = blockIdx.x;
    int t = threadIdx.x;
    float c = fmaxf(g_cnt[gph], 1.0f);
    pl[t] = g_P[gph * 128 + t] / c;
    __syncthreads();
    float acc = b1[t];
    for (int k = 0; k < 128; k++) acc = fmaf(pl[k], W1[k * 128 + t], acc);
    float s = gn[t] * rsqrtf(1.0f + EPSBN);
    o1[t] = fmaxf(fmaf(acc, s, be[t]), 0.f);
    __syncthreads();
    float acc2 = b2[t];
    for (int k = 0; k < 128; k++) acc2 = fmaf(o1[k], W2[k * 128 + t], acc2);
    out[gph * 128 + t] = acc2;
}

// ---------------- launch ---------------------------------------------------------
extern "C" void kernel_launch(void* const* d_in, const int* in_sizes, int n_in,
                              void* d_out, int out_size)
{
    const float* x       = (const float*)d_in[0];
    const void*  ei      = d_in[1];
    const float* ea      = (const float*)d_in[2];
    const float* pos     = (const float*)d_in[3];
    const void*  bt      = d_in[4];
    const float* Wi      = (const float*)d_in[5];
    const float* bi      = (const float*)d_in[6];
    const float* node_W  = (const float*)d_in[7];
    const float* node_b  = (const float*)d_in[8];
    const float* msg_W1  = (const float*)d_in[9];
    const float* msg_b1  = (const float*)d_in[10];
    const float* msg_g   = (const float*)d_in[11];
    const float* msg_be  = (const float*)d_in[12];
    const float* msg_W2  = (const float*)d_in[13];
    const float* msg_b2  = (const float*)d_in[14];
    const float* out_W1  = (const float*)d_in[15];
    const float* out_b1  = (const float*)d_in[16];
    const float* out_g   = (const float*)d_in[17];
    const float* out_be  = (const float*)d_in[18];
    const float* out_W2  = (const float*)d_in[19];
    const float* out_b2  = (const float*)d_in[20];

    int N = in_sizes[3] / 3;   // pos [N,3]
    int E = in_sizes[1] / 2;   // edge_index [2,E]

    void *hp, *Sp, *Pp, *cp, *whip, *wlop;
    cudaGetSymbolAddress(&hp, g_h);
    cudaGetSymbolAddress(&Sp, g_S);
    cudaGetSymbolAddress(&Pp, g_P);
    cudaGetSymbolAddress(&cp, g_cnt);
    cudaGetSymbolAddress(&whip, g_Whi);
    cudaGetSymbolAddress(&wlop, g_Wlo);
    const float* Whi = (const float*)whip;
    const float* Wlo = (const float*)wlop;

    detect_kernel<<<1, 256>>>(ei, bt, N, E);
    int mx = (N > E ? N : E);
    convert_kernel<<<(mx + 255) / 256, 256>>>(ei, bt, N, E);
    deg_kernel<<<(E + 255) / 256, 256>>>(E);
    split_weights<<<(WTOT + 255) / 256, 256>>>(Wi, msg_W1, node_W, msg_W2);

    int nT = (N + 63) / 64;
    int eT = (E + 63) / 64;

    // h = x @ Wi + bi
    gemm64<<<nT, 256>>>(x, 256, Whi, Wlo, bi, (float*)hp, N, 256);

    for (int l = 0; l < 3; l++) {
        const float* W1l   = msg_W1 + (size_t)l * 323 * 128;
        const float* W1hi  = Whi + OFF_W1 + (size_t)l * TW1;
        const float* W1lo  = Wlo + OFF_W1 + (size_t)l * TW1;
        const float* NWhi  = Whi + OFF_NW + (size_t)l * 16384;
        const float* NWlo  = Wlo + OFF_NW + (size_t)l * 16384;
        const float* W2hi  = Whi + OFF_W2 + (size_t)l * 16384;
        const float* W2lo  = Wlo + OFF_W2 + (size_t)l * 16384;

        // A = h@W1a, B = h@W1b, U = h@nodeW + node_b (one fused launch)
        gemm_h3<<<dim3(nT, 3), 256>>>(W1hi, W1lo,
                                      W1hi + 128 * 128, W1lo + 128 * 128,
                                      NWhi, NWlo,
                                      node_b + l * 128, N);
        cudaMemsetAsync(Sp, 0, (size_t)N * 128 * sizeof(float));
        edge_fused<<<eT, 256>>>(ea, pos, W1l,
                                W1hi + 256 * 128, W1lo + 256 * 128,
                                msg_g + l * 128, msg_be + l * 128,
                                msg_b1 + l * 128, E);
        node1<<<nT, 256>>>(W2hi, W2lo, msg_b2 + l * 128,
                           msg_g + l * 128, msg_be + l * 128,
                           msg_b1 + l * 128, N);
    }

    cudaMemsetAsync(Pp, 0, GG * 128 * sizeof(float));
    cudaMemsetAsync(cp, 0, GG * sizeof(float));
    pool_kernel<<<(N * 32 + 255) / 256, 256>>>(N);
    head_kernel<<<GG, 128>>>(out_W1, out_b1, out_g, out_be, out_W2, out_b2,
                             (float*)d_out);
}

// round 12
// speedup vs baseline: 1.0931x; 1.0931x over previous
#include <cuda_runtime.h>
#include <math.h>

#define NN 50000
#define EE 400000
#define GG 64
#define EPSBN 1e-5f
#define APAD 20    // A tile row stride (floats)
#define BPAD 136   // B tile row stride (floats)
#define SPAD 132   // staging tile row stride

// ---------------- scratch ------------------------------------------------------
__device__ float g_h[NN * 128];
__device__ float g_Ab[NN * 128];
__device__ float g_Bb[NN * 128];
__device__ float g_U[NN * 128];
__device__ float g_S[NN * 128];
__device__ int   g_src[EE];
__device__ int   g_dst[EE];
__device__ int   g_batch[NN];
__device__ float g_deg[NN];
__device__ float g_P[GG * 128];
__device__ float g_cnt[GG];
__device__ int   g_e64;
__device__ int   g_b64;

// ---------------- dtype detection ----------------------------------------------
__global__ void detect_kernel(const void* ei, const void* bt, int N, int E) {
    __shared__ int s_e, s_b;
    int t = threadIdx.x;
    if (t == 0) { s_e = 1; s_b = 1; }
    __syncthreads();
    const long long* p = (const long long*)ei;
    long long v = p[t];
    if (v < 0 || v >= (long long)N) s_e = 0;
    int base = N / 2 - 256; if (base < 0) base = 0;
    const long long* q = (const long long*)bt;
    long long w = q[base + t];
    if (w < 0 || w >= (long long)GG) s_b = 0;
    __syncthreads();
    if (t == 0) { g_e64 = s_e; g_b64 = s_b; }
}

__global__ void convert_kernel(const void* ei, const void* bt, int N, int E) {
    int i = blockIdx.x * blockDim.x + threadIdx.x;
    int e64 = g_e64, b64 = g_b64;
    if (i < E) {
        if (e64) {
            const long long* p = (const long long*)ei;
            g_src[i] = (int)p[i];
            g_dst[i] = (int)p[E + i];
        } else {
            const int* p = (const int*)ei;
            g_src[i] = p[i];
            g_dst[i] = p[E + i];
        }
    }
    if (i < N) {
        if (b64) g_batch[i] = (int)((const long long*)bt)[i];
        else     g_batch[i] = ((const int*)bt)[i];
        g_deg[i] = 1.0f;   // self loop
    }
}

__global__ void deg_kernel(int E) {
    int i = blockIdx.x * blockDim.x + threadIdx.x;
    if (i < E) atomicAdd(&g_deg[g_dst[i]], 1.0f);
}

// ---------------- tf32 helpers --------------------------------------------------
__device__ __forceinline__ void tf32_split_u(float v, unsigned& hi, unsigned& lo) {
    asm("cvt.rna.tf32.f32 %0, %1;" : "=r"(hi) : "f"(v));
    float l = v - __uint_as_float(hi);
    asm("cvt.rna.tf32.f32 %0, %1;" : "=r"(lo) : "f"(l));
}

__device__ __forceinline__ void tf32_split_f(float v, float& hi, float& lo) {
    unsigned u;
    asm("cvt.rna.tf32.f32 %0, %1;" : "=r"(u) : "f"(v));
    hi = __uint_as_float(u);
    float l = v - hi;
    asm("cvt.rna.tf32.f32 %0, %1;" : "=r"(u) : "f"(l));
    lo = __uint_as_float(u);
}

#define MMA_TF32(d, a, b)                                              \
    asm volatile("mma.sync.aligned.m16n8k8.row.col.f32.tf32.tf32.f32 " \
        "{%0,%1,%2,%3}, {%4,%5,%6,%7}, {%8,%9}, {%0,%1,%2,%3};"        \
        : "+f"((d)[0]), "+f"((d)[1]), "+f"((d)[2]), "+f"((d)[3])       \
        : "r"((a)[0]), "r"((a)[1]), "r"((a)[2]), "r"((a)[3]),          \
          "r"((b)[0]), "r"((b)[1]))

// fragment-load (split A from pre-split smem, split B in-register), M64xN128
#define MMA_SLAB(sAhi, sAlo, sB, acc)                                           \
    _Pragma("unroll")                                                           \
    for (int kk = 0; kk < 16; kk += 8) {                                        \
        unsigned ahi[2][4], alo[2][4], bhi[4][2], blo[4][2];                    \
        _Pragma("unroll")                                                       \
        for (int mt = 0; mt < 2; mt++) {                                        \
            int base = (wm + mt * 16 + g) * APAD + kk + tg;                     \
            ahi[mt][0] = __float_as_uint(sAhi[base]);                           \
            ahi[mt][1] = __float_as_uint(sAhi[base + 8 * APAD]);                \
            ahi[mt][2] = __float_as_uint(sAhi[base + 4]);                       \
            ahi[mt][3] = __float_as_uint(sAhi[base + 8 * APAD + 4]);            \
            alo[mt][0] = __float_as_uint(sAlo[base]);                           \
            alo[mt][1] = __float_as_uint(sAlo[base + 8 * APAD]);                \
            alo[mt][2] = __float_as_uint(sAlo[base + 4]);                       \
            alo[mt][3] = __float_as_uint(sAlo[base + 8 * APAD + 4]);            \
        }                                                                       \
        _Pragma("unroll")                                                       \
        for (int nt = 0; nt < 4; nt++) {                                        \
            int n = wn + nt * 8 + g;                                            \
            tf32_split_u(sB[(kk + tg) * BPAD + n],     bhi[nt][0], blo[nt][0]); \
            tf32_split_u(sB[(kk + tg + 4) * BPAD + n], bhi[nt][1], blo[nt][1]); \
        }                                                                       \
        _Pragma("unroll")                                                       \
        for (int mt = 0; mt < 2; mt++)                                          \
            _Pragma("unroll")                                                   \
            for (int nt = 0; nt < 4; nt++) {                                    \
                MMA_TF32(acc[mt][nt], ahi[mt], bhi[nt]);                        \
                MMA_TF32(acc[mt][nt], ahi[mt], blo[nt]);                        \
                MMA_TF32(acc[mt][nt], alo[mt], bhi[nt]);                        \
            }                                                                   \
    }

// split a float4 into hi/lo float4s
__device__ __forceinline__ void split4(const float4& v, float4& hi, float4& lo) {
    tf32_split_f(v.x, hi.x, lo.x);
    tf32_split_f(v.y, hi.y, lo.y);
    tf32_split_f(v.z, hi.z, lo.z);
    tf32_split_f(v.w, hi.w, lo.w);
}

// ---------------- generic GEMM (init): C[M,128] = A[M,K]@W + bias, M-tile 64 ---
__global__ __launch_bounds__(256) void gemm64(
    const float* __restrict__ Ap, int lda,
    const float* __restrict__ Wp, const float* __restrict__ bias,
    float* __restrict__ Cp, int M, int K)
{
    __shared__ __align__(16) float sAhi[64 * APAD], sAlo[64 * APAD];
    __shared__ __align__(16) float sB[16 * BPAD];
    int t = threadIdx.x, lane = t & 31, w = t >> 5;
    int wm = (w & 1) * 32, wn = (w >> 1) * 32;
    int g = lane >> 2, tg = lane & 3;
    int m0 = blockIdx.x * 64;
    int arow = t >> 2, akq = t & 3;
    int bkr = t >> 4, bn4 = (t & 15) * 8;
    int gm = m0 + arow;
    float acc[2][4][4];
#pragma unroll
    for (int a = 0; a < 2; a++)
#pragma unroll
        for (int b = 0; b < 4; b++)
#pragma unroll
            for (int c = 0; c < 4; c++) acc[a][b][c] = 0.f;

    float4 va = make_float4(0.f, 0.f, 0.f, 0.f);
    if (gm < M) va = *(const float4*)(Ap + (size_t)gm * lda + akq * 4);
    float4 vb0 = *(const float4*)(Wp + (size_t)bkr * 128 + bn4);
    float4 vb1 = *(const float4*)(Wp + (size_t)bkr * 128 + bn4 + 4);

    for (int k0 = 0; k0 < K; k0 += 16) {
        float4 ahi4, alo4;
        split4(va, ahi4, alo4);
        *(float4*)&sAhi[arow * APAD + akq * 4] = ahi4;
        *(float4*)&sAlo[arow * APAD + akq * 4] = alo4;
        *(float4*)&sB[bkr * BPAD + bn4]      = vb0;
        *(float4*)&sB[bkr * BPAD + bn4 + 4]  = vb1;
        __syncthreads();
        int kn = k0 + 16;
        if (kn < K) {
            va = make_float4(0.f, 0.f, 0.f, 0.f);
            if (gm < M) va = *(const float4*)(Ap + (size_t)gm * lda + kn + akq * 4);
            vb0 = *(const float4*)(Wp + (size_t)(kn + bkr) * 128 + bn4);
            vb1 = *(const float4*)(Wp + (size_t)(kn + bkr) * 128 + bn4 + 4);
        }
        MMA_SLAB(sAhi, sAlo, sB, acc)
        __syncthreads();
    }
#pragma unroll
    for (int mt = 0; mt < 2; mt++) {
        int r0 = m0 + wm + mt * 16 + g;
#pragma unroll
        for (int nt = 0; nt < 4; nt++) {
            int c = wn + nt * 8 + 2 * tg;
            float b0 = bias ? bias[c] : 0.f;
            float b1 = bias ? bias[c + 1] : 0.f;
            if (r0 < M) {
                Cp[(size_t)r0 * 128 + c]     = acc[mt][nt][0] + b0;
                Cp[(size_t)r0 * 128 + c + 1] = acc[mt][nt][1] + b1;
            }
            if (r0 + 8 < M) {
                Cp[(size_t)(r0 + 8) * 128 + c]     = acc[mt][nt][2] + b0;
                Cp[(size_t)(r0 + 8) * 128 + c + 1] = acc[mt][nt][3] + b1;
            }
        }
    }
}

// ------- fused node GEMMs: y=0: A=h@W1a, y=1: B=h@W1b, y=2: U=h@nodeW+node_b ---
__global__ __launch_bounds__(256) void gemm_h3(
    const float* __restrict__ Wa, const float* __restrict__ Wb,
    const float* __restrict__ Wn, const float* __restrict__ nodeB, int M)
{
    __shared__ __align__(16) float sAhi[64 * APAD], sAlo[64 * APAD];
    __shared__ __align__(16) float sB[16 * BPAD];
    int y = blockIdx.y;
    const float* Wp = (y == 0) ? Wa : ((y == 1) ? Wb : Wn);
    float* Cp = (y == 0) ? g_Ab : ((y == 1) ? g_Bb : g_U);
    const float* bias = (y == 2) ? nodeB : 0;

    int t = threadIdx.x, lane = t & 31, w = t >> 5;
    int wm = (w & 1) * 32, wn = (w >> 1) * 32;
    int g = lane >> 2, tg = lane & 3;
    int m0 = blockIdx.x * 64;
    int arow = t >> 2, akq = t & 3;
    int bkr = t >> 4, bn4 = (t & 15) * 8;
    int gm = m0 + arow;
    float acc[2][4][4];
#pragma unroll
    for (int a = 0; a < 2; a++)
#pragma unroll
        for (int b = 0; b < 4; b++)
#pragma unroll
            for (int c = 0; c < 4; c++) acc[a][b][c] = 0.f;

    float4 va = make_float4(0.f, 0.f, 0.f, 0.f);
    if (gm < M) va = *(const float4*)(g_h + (size_t)gm * 128 + akq * 4);
    float4 vb0 = *(const float4*)(Wp + (size_t)bkr * 128 + bn4);
    float4 vb1 = *(const float4*)(Wp + (size_t)bkr * 128 + bn4 + 4);

    for (int k0 = 0; k0 < 128; k0 += 16) {
        float4 ahi4, alo4;
        split4(va, ahi4, alo4);
        *(float4*)&sAhi[arow * APAD + akq * 4] = ahi4;
        *(float4*)&sAlo[arow * APAD + akq * 4] = alo4;
        *(float4*)&sB[bkr * BPAD + bn4]      = vb0;
        *(float4*)&sB[bkr * BPAD + bn4 + 4]  = vb1;
        __syncthreads();
        int kn = k0 + 16;
        if (kn < 128) {
            va = make_float4(0.f, 0.f, 0.f, 0.f);
            if (gm < M) va = *(const float4*)(g_h + (size_t)gm * 128 + kn + akq * 4);
            vb0 = *(const float4*)(Wp + (size_t)(kn + bkr) * 128 + bn4);
            vb1 = *(const float4*)(Wp + (size_t)(kn + bkr) * 128 + bn4 + 4);
        }
        MMA_SLAB(sAhi, sAlo, sB, acc)
        __syncthreads();
    }
#pragma unroll
    for (int mt = 0; mt < 2; mt++) {
        int r0 = m0 + wm + mt * 16 + g;
#pragma unroll
        for (int nt = 0; nt < 4; nt++) {
            int c = wn + nt * 8 + 2 * tg;
            float b0 = bias ? bias[c] : 0.f;
            float b1 = bias ? bias[c + 1] : 0.f;
            if (r0 < M) {
                Cp[(size_t)r0 * 128 + c]     = acc[mt][nt][0] + b0;
                Cp[(size_t)r0 * 128 + c + 1] = acc[mt][nt][1] + b1;
            }
            if (r0 + 8 < M) {
                Cp[(size_t)(r0 + 8) * 128 + c]     = acc[mt][nt][2] + b0;
                Cp[(size_t)(r0 + 8) * 128 + c + 1] = acc[mt][nt][3] + b1;
            }
        }
    }
}

// ------- fused edge pass: GEMM(ea@W1c) + gather A/B/relpos + BN/ReLU + scatter --
__global__ __launch_bounds__(256) void edge_fused(
    const float* __restrict__ ea, const float* __restrict__ pos,
    const float* __restrict__ W1,
    const float* __restrict__ gn, const float* __restrict__ be,
    const float* __restrict__ b1, int E)
{
    __shared__ __align__(16) float sAhi[64 * APAD], sAlo[64 * APAD];
    __shared__ __align__(16) float sB[16 * BPAD];
    __shared__ __align__(16) float stage[64 * SPAD];
    __shared__ __align__(16) float w1d[3 * 128];
    __shared__ __align__(16) float sc[128], sh[128];
    __shared__ float srp[64 * 3];
    __shared__ int   sdst[64], ssrc[64];

    int t = threadIdx.x, lane = t & 31, w = t >> 5;
    int wm = (w & 1) * 32, wn = (w >> 1) * 32;
    int g = lane >> 2, tg = lane & 3;
    int m0 = blockIdx.x * 64;

    if (t < 128) {
        float s = gn[t] * rsqrtf(1.0f + EPSBN);
        sc[t] = s;
        sh[t] = fmaf(b1[t], s, be[t]);
        w1d[t]       = W1[320 * 128 + t];
        w1d[128 + t] = W1[321 * 128 + t];
        w1d[256 + t] = W1[322 * 128 + t];
    }
    if (t < 64) {
        int e = m0 + t;
        int s = 0, d = 0;
        float r0 = 0.f, r1 = 0.f, r2 = 0.f;
        if (e < E) {
            s = g_src[e]; d = g_dst[e];
            r0 = pos[d * 3 + 0] - pos[s * 3 + 0];
            r1 = pos[d * 3 + 1] - pos[s * 3 + 1];
            r2 = pos[d * 3 + 2] - pos[s * 3 + 2];
        }
        ssrc[t] = s; sdst[t] = d;
        srp[t * 3 + 0] = r0; srp[t * 3 + 1] = r1; srp[t * 3 + 2] = r2;
    }

    const float* Wc = W1 + 256 * 128;
    int arow = t >> 2, akq = t & 3;
    int bkr = t >> 4, bn4 = (t & 15) * 8;
    int ge = m0 + arow;
    float acc[2][4][4];
#pragma unroll
    for (int a = 0; a < 2; a++)
#pragma unroll
        for (int b = 0; b < 4; b++)
#pragma unroll
            for (int c = 0; c < 4; c++) acc[a][b][c] = 0.f;

    float4 va = make_float4(0.f, 0.f, 0.f, 0.f);
    if (ge < E) va = *(const float4*)(ea + (size_t)ge * 64 + akq * 4);
    float4 vb0 = *(const float4*)(Wc + (size_t)bkr * 128 + bn4);
    float4 vb1 = *(const float4*)(Wc + (size_t)bkr * 128 + bn4 + 4);

    for (int k0 = 0; k0 < 64; k0 += 16) {
        float4 ahi4, alo4;
        split4(va, ahi4, alo4);
        *(float4*)&sAhi[arow * APAD + akq * 4] = ahi4;
        *(float4*)&sAlo[arow * APAD + akq * 4] = alo4;
        *(float4*)&sB[bkr * BPAD + bn4]      = vb0;
        *(float4*)&sB[bkr * BPAD + bn4 + 4]  = vb1;
        __syncthreads();
        int kn = k0 + 16;
        if (kn < 64) {
            va = make_float4(0.f, 0.f, 0.f, 0.f);
            if (ge < E) va = *(const float4*)(ea + (size_t)ge * 64 + kn + akq * 4);
            vb0 = *(const float4*)(Wc + (size_t)(kn + bkr) * 128 + bn4);
            vb1 = *(const float4*)(Wc + (size_t)(kn + bkr) * 128 + bn4 + 4);
        }
        MMA_SLAB(sAhi, sAlo, sB, acc)
        __syncthreads();
    }

    // single staging pass: every warp writes its (row,col) patch; one sync
#pragma unroll
    for (int mt = 0; mt < 2; mt++)
#pragma unroll
        for (int nt = 0; nt < 4; nt++)
#pragma unroll
            for (int half = 0; half < 2; half++) {
                int el = wm + mt * 16 + g + half * 8;   // 0..63
                int c = wn + nt * 8 + 2 * tg;
                stage[el * SPAD + c]     = acc[mt][nt][half * 2 + 0];
                stage[el * SPAD + c + 1] = acc[mt][nt][half * 2 + 1];
            }
    __syncthreads();

    // scatter: each warp handles 8 independent edges (deep MLP)
    {
        int j = lane * 4;
        float4 scv = *(const float4*)&sc[j];
        float4 shv = *(const float4*)&sh[j];
        float4 w0 = *(const float4*)&w1d[j];
        float4 w1v = *(const float4*)&w1d[128 + j];
        float4 w2 = *(const float4*)&w1d[256 + j];
#pragma unroll
        for (int i = 0; i < 8; i++) {
            int el = w * 8 + i;                 // 0..63
            int eg = m0 + el;
            if (eg < E) {
                int d = sdst[el], s2 = ssrc[el];
                float rp0 = srp[el * 3 + 0];
                float rp1 = srp[el * 3 + 1];
                float rp2 = srp[el * 3 + 2];
                float4 cv = *(const float4*)&stage[el * SPAD + j];
                float4 av = *(const float4*)&g_Ab[(size_t)d * 128 + j];
                float4 bv = *(const float4*)&g_Bb[(size_t)s2 * 128 + j];
                float m0v = cv.x + av.x + bv.x + rp0 * w0.x + rp1 * w1v.x + rp2 * w2.x;
                float m1v = cv.y + av.y + bv.y + rp0 * w0.y + rp1 * w1v.y + rp2 * w2.y;
                float m2v = cv.z + av.z + bv.z + rp0 * w0.z + rp1 * w1v.z + rp2 * w2.z;
                float m3v = cv.w + av.w + bv.w + rp0 * w0.w + rp1 * w1v.w + rp2 * w2.w;
                float r0 = fmaxf(fmaf(m0v, scv.x, shv.x), 0.f);
                float r1 = fmaxf(fmaf(m1v, scv.y, shv.y), 0.f);
                float r2 = fmaxf(fmaf(m2v, scv.z, shv.z), 0.f);
                float r3 = fmaxf(fmaf(m3v, scv.w, shv.w), 0.f);
                float* pS = &g_S[(size_t)d * 128 + j];
                asm volatile("red.global.add.v4.f32 [%0], {%1, %2, %3, %4};"
                             :: "l"(pS), "f"(r0), "f"(r1), "f"(r2), "f"(r3) : "memory");
            }
        }
    }
}

// ------- node update: h += relu( U + (S + selfmsg)@W2 + deg*b2 ) ---------------
__global__ __launch_bounds__(256) void node1(
    const float* __restrict__ W2, const float* __restrict__ b2,
    const float* __restrict__ gn, const float* __restrict__ be,
    const float* __restrict__ b1, int M)
{
    __shared__ __align__(16) float sAhi[64 * APAD], sAlo[64 * APAD];
    __shared__ __align__(16) float sB[16 * BPAD];
    __shared__ float sc[128], sh[128], b2s[128];
    int t = threadIdx.x, lane = t & 31, w = t >> 5;
    if (t < 128) {
        float s = gn[t] * rsqrtf(1.0f + EPSBN);
        sc[t] = s;
        sh[t] = fmaf(b1[t], s, be[t]);
        b2s[t] = b2[t];
    }
    __syncthreads();
    int wm = (w & 1) * 32, wn = (w >> 1) * 32;
    int g = lane >> 2, tg = lane & 3;
    int m0 = blockIdx.x * 64;
    int arow = t >> 2, akq = t & 3;
    int bkr = t >> 4, bn4 = (t & 15) * 8;
    int gm = m0 + arow;
    float acc[2][4][4];
#pragma unroll
    for (int a = 0; a < 2; a++)
#pragma unroll
        for (int b = 0; b < 4; b++)
#pragma unroll
            for (int c = 0; c < 4; c++) acc[a][b][c] = 0.f;

    // prefetch raw vectors for k0=0
    float4 pv_s = make_float4(0.f, 0.f, 0.f, 0.f);
    float4 pv_a = pv_s, pv_b = pv_s;
    if (gm < M) {
        pv_s = *(const float4*)(g_S  + (size_t)gm * 128 + akq * 4);
        pv_a = *(const float4*)(g_Ab + (size_t)gm * 128 + akq * 4);
        pv_b = *(const float4*)(g_Bb + (size_t)gm * 128 + akq * 4);
    }
    float4 vb0 = *(const float4*)(W2 + (size_t)bkr * 128 + bn4);
    float4 vb1 = *(const float4*)(W2 + (size_t)bkr * 128 + bn4 + 4);

    for (int k0 = 0; k0 < 128; k0 += 16) {
        // build A values: S + relu(bn(A+B)) (self-loop message), split, store
        {
            float4 out;
            float* sp = (float*)&pv_s; float* ap = (float*)&pv_a;
            float* bp = (float*)&pv_b; float* op = (float*)&out;
#pragma unroll
            for (int j = 0; j < 4; j++) {
                int k = k0 + akq * 4 + j;
                float r = fmaxf(fmaf(ap[j] + bp[j], sc[k], sh[k]), 0.f);
                op[j] = sp[j] + r;
            }
            float4 ahi4, alo4;
            split4(out, ahi4, alo4);
            *(float4*)&sAhi[arow * APAD + akq * 4] = ahi4;
            *(float4*)&sAlo[arow * APAD + akq * 4] = alo4;
        }
        *(float4*)&sB[bkr * BPAD + bn4]     = vb0;
        *(float4*)&sB[bkr * BPAD + bn4 + 4] = vb1;
        __syncthreads();
        int kn = k0 + 16;
        if (kn < 128) {
            pv_s = make_float4(0.f, 0.f, 0.f, 0.f);
            pv_a = pv_s; pv_b = pv_s;
            if (gm < M) {
                pv_s = *(const float4*)(g_S  + (size_t)gm * 128 + kn + akq * 4);
                pv_a = *(const float4*)(g_Ab + (size_t)gm * 128 + kn + akq * 4);
                pv_b = *(const float4*)(g_Bb + (size_t)gm * 128 + kn + akq * 4);
            }
            vb0 = *(const float4*)(W2 + (size_t)(kn + bkr) * 128 + bn4);
            vb1 = *(const float4*)(W2 + (size_t)(kn + bkr) * 128 + bn4 + 4);
        }
        MMA_SLAB(sAhi, sAlo, sB, acc)
        __syncthreads();
    }
#pragma unroll
    for (int mt = 0; mt < 2; mt++) {
        int r0 = m0 + wm + mt * 16 + g;
#pragma unroll
        for (int nt = 0; nt < 4; nt++) {
            int c = wn + nt * 8 + 2 * tg;
#pragma unroll
            for (int half = 0; half < 2; half++) {
                int rr = r0 + half * 8;
                if (rr < M) {
                    float dg = g_deg[rr];
                    float u0 = g_U[(size_t)rr * 128 + c];
                    float u1 = g_U[(size_t)rr * 128 + c + 1];
                    float v0 = acc[mt][nt][half * 2 + 0] + u0 + dg * b2s[c];
                    float v1 = acc[mt][nt][half * 2 + 1] + u1 + dg * b2s[c + 1];
                    g_h[(size_t)rr * 128 + c]     += fmaxf(v0, 0.f);
                    g_h[(size_t)rr * 128 + c + 1] += fmaxf(v1, 0.f);
                }
            }
        }
    }
}

// ---------------- pooling + output MLP ------------------------------------------
__global__ void pool_kernel(int N) {
    int w = (blockIdx.x * blockDim.x + threadIdx.x) >> 5;
    int lane = threadIdx.x & 31;
    if (w >= N) return;
    int gph = g_batch[w];
    int j = lane * 4;
    float4 v = *(const float4*)&g_h[(size_t)w * 128 + j];
    float* p = &g_P[(size_t)gph * 128 + j];
    asm volatile("red.global.add.v4.f32 [%0], {%1, %2, %3, %4};"
                 :: "l"(p), "f"(v.x), "f"(v.y), "f"(v.z), "f"(v.w) : "memory");
    if (lane == 0) atomicAdd(&g_cnt[gph], 1.0f);
}

__global__ void head_kernel(
    const float* __restrict__ W1, const float* __restrict__ b1,
    const float* __restrict__ gn, const float* __restrict__ be,
    const float* __restrict__ W2, const float* __restrict__ b2,
    float* __restrict__ out)
{
    __shared__ float pl[128], o1[128];
    int gph = blockIdx.x;
    int t = threadIdx.x;
    float c = fmaxf(g_cnt[gph], 1.0f);
    pl[t] = g_P[gph * 128 + t] / c;
    __syncthreads();
    float acc = b1[t];
    for (int k = 0; k < 128; k++) acc = fmaf(pl[k], W1[k * 128 + t], acc);
    float s = gn[t] * rsqrtf(1.0f + EPSBN);
    o1[t] = fmaxf(fmaf(acc, s, be[t]), 0.f);
    __syncthreads();
    float acc2 = b2[t];
    for (int k = 0; k < 128; k++) acc2 = fmaf(o1[k], W2[k * 128 + t], acc2);
    out[gph * 128 + t] = acc2;
}

// ---------------- launch ---------------------------------------------------------
extern "C" void kernel_launch(void* const* d_in, const int* in_sizes, int n_in,
                              void* d_out, int out_size)
{
    const float* x       = (const float*)d_in[0];
    const void*  ei      = d_in[1];
    const float* ea      = (const float*)d_in[2];
    const float* pos     = (const float*)d_in[3];
    const void*  bt      = d_in[4];
    const float* Wi      = (const float*)d_in[5];
    const float* bi      = (const float*)d_in[6];
    const float* node_W  = (const float*)d_in[7];
    const float* node_b  = (const float*)d_in[8];
    const float* msg_W1  = (const float*)d_in[9];
    const float* msg_b1  = (const float*)d_in[10];
    const float* msg_g   = (const float*)d_in[11];
    const float* msg_be  = (const float*)d_in[12];
    const float* msg_W2  = (const float*)d_in[13];
    const float* msg_b2  = (const float*)d_in[14];
    const float* out_W1  = (const float*)d_in[15];
    const float* out_b1  = (const float*)d_in[16];
    const float* out_g   = (const float*)d_in[17];
    const float* out_be  = (const float*)d_in[18];
    const float* out_W2  = (const float*)d_in[19];
    const float* out_b2  = (const float*)d_in[20];

    int N = in_sizes[3] / 3;   // pos [N,3]
    int E = in_sizes[1] / 2;   // edge_index [2,E]

    void *hp, *Sp, *Pp, *cp;
    cudaGetSymbolAddress(&hp, g_h);
    cudaGetSymbolAddress(&Sp, g_S);
    cudaGetSymbolAddress(&Pp, g_P);
    cudaGetSymbolAddress(&cp, g_cnt);

    detect_kernel<<<1, 256>>>(ei, bt, N, E);
    int mx = (N > E ? N : E);
    convert_kernel<<<(mx + 255) / 256, 256>>>(ei, bt, N, E);
    deg_kernel<<<(E + 255) / 256, 256>>>(E);

    int nT = (N + 63) / 64;
    int eT = (E + 63) / 64;

    // h = x @ Wi + bi
    gemm64<<<nT, 256>>>(x, 256, Wi, bi, (float*)hp, N, 256);

    for (int l = 0; l < 3; l++) {
        const float* W1l = msg_W1 + (size_t)l * 323 * 128;
        // A = h@W1a, B = h@W1b, U = h@nodeW + node_b (one fused launch)
        gemm_h3<<<dim3(nT, 3), 256>>>(W1l, W1l + 128 * 128,
                                      node_W + (size_t)l * 128 * 128,
                                      node_b + l * 128, N);
        cudaMemsetAsync(Sp, 0, (size_t)N * 128 * sizeof(float));
        edge_fused<<<eT, 256>>>(ea, pos, W1l,
                                msg_g + l * 128, msg_be + l * 128,
                                msg_b1 + l * 128, E);
        node1<<<nT, 256>>>(msg_W2 + (size_t)l * 128 * 128, msg_b2 + l * 128,
                           msg_g + l * 128, msg_be + l * 128,
                           msg_b1 + l * 128, N);
    }

    cudaMemsetAsync(Pp, 0, GG * 128 * sizeof(float));
    cudaMemsetAsync(cp, 0, GG * sizeof(float));
    pool_kernel<<<(N * 32 + 255) / 256, 256>>>(N);
    head_kernel<<<GG, 128>>>(out_W1, out_b1, out_g, out_be, out_W2, out_b2,
                             (float*)d_out);
}

// round 13
// speedup vs baseline: 1.1196x; 1.0242x over previous
#include <cuda_runtime.h>
#include <math.h>

#define NN 50000
#define EE 400000
#define GG 64
#define EPSBN 1e-5f
#define APAD 20    // A tile row stride (floats)
#define BPAD 136   // B tile row stride (floats)
#define SPAD 132   // staging tile row stride

// ---------------- scratch ------------------------------------------------------
__device__ float g_h[NN * 128];
__device__ float g_Ab[NN * 128];
__device__ float g_Bb[NN * 128];
__device__ float g_U[NN * 128];
__device__ float g_S[NN * 128];
__device__ int   g_src[EE];
__device__ int   g_dst[EE];
__device__ int   g_batch[NN];
__device__ float g_deg[NN];
__device__ float g_P[GG * 128];
__device__ float g_cnt[GG];
__device__ int   g_e64;
__device__ int   g_b64;

// ---------------- dtype detection ----------------------------------------------
__global__ void detect_kernel(const void* ei, const void* bt, int N, int E) {
    __shared__ int s_e, s_b;
    int t = threadIdx.x;
    if (t == 0) { s_e = 1; s_b = 1; }
    __syncthreads();
    const long long* p = (const long long*)ei;
    long long v = p[t];
    if (v < 0 || v >= (long long)N) s_e = 0;
    int base = N / 2 - 256; if (base < 0) base = 0;
    const long long* q = (const long long*)bt;
    long long w = q[base + t];
    if (w < 0 || w >= (long long)GG) s_b = 0;
    __syncthreads();
    if (t == 0) { g_e64 = s_e; g_b64 = s_b; }
}

__global__ void convert_kernel(const void* ei, const void* bt, int N, int E) {
    int i = blockIdx.x * blockDim.x + threadIdx.x;
    int e64 = g_e64, b64 = g_b64;
    if (i < E) {
        if (e64) {
            const long long* p = (const long long*)ei;
            g_src[i] = (int)p[i];
            g_dst[i] = (int)p[E + i];
        } else {
            const int* p = (const int*)ei;
            g_src[i] = p[i];
            g_dst[i] = p[E + i];
        }
    }
    if (i < N) {
        if (b64) g_batch[i] = (int)((const long long*)bt)[i];
        else     g_batch[i] = ((const int*)bt)[i];
        g_deg[i] = 1.0f;   // self loop
    }
}

__global__ void deg_kernel(int E) {
    int i = blockIdx.x * blockDim.x + threadIdx.x;
    if (i < E) atomicAdd(&g_deg[g_dst[i]], 1.0f);
}

// ---------------- tf32 helpers --------------------------------------------------
__device__ __forceinline__ void tf32_split_u(float v, unsigned& hi, unsigned& lo) {
    asm("cvt.rna.tf32.f32 %0, %1;" : "=r"(hi) : "f"(v));
    float l = v - __uint_as_float(hi);
    asm("cvt.rna.tf32.f32 %0, %1;" : "=r"(lo) : "f"(l));
}

#define MMA_TF32(d, a, b)                                              \
    asm volatile("mma.sync.aligned.m16n8k8.row.col.f32.tf32.tf32.f32 " \
        "{%0,%1,%2,%3}, {%4,%5,%6,%7}, {%8,%9}, {%0,%1,%2,%3};"        \
        : "+f"((d)[0]), "+f"((d)[1]), "+f"((d)[2]), "+f"((d)[3])       \
        : "r"((a)[0]), "r"((a)[1]), "r"((a)[2]), "r"((a)[3]),          \
          "r"((b)[0]), "r"((b)[1]))

// fragment-load (fp32 smem) + in-register split + 3xTF32 MMA, M64xN128 tiling
#define MMA_SLAB(sA, sB, acc)                                                   \
    _Pragma("unroll")                                                           \
    for (int kk = 0; kk < 16; kk += 8) {                                        \
        unsigned ahi[2][4], alo[2][4], bhi[4][2], blo[4][2];                    \
        _Pragma("unroll")                                                       \
        for (int mt = 0; mt < 2; mt++) {                                        \
            int base = (wm + mt * 16 + g) * APAD + kk + tg;                     \
            tf32_split_u((sA)[base],                ahi[mt][0], alo[mt][0]);    \
            tf32_split_u((sA)[base + 8 * APAD],     ahi[mt][1], alo[mt][1]);    \
            tf32_split_u((sA)[base + 4],            ahi[mt][2], alo[mt][2]);    \
            tf32_split_u((sA)[base + 8 * APAD + 4], ahi[mt][3], alo[mt][3]);    \
        }                                                                       \
        _Pragma("unroll")                                                       \
        for (int nt = 0; nt < 4; nt++) {                                        \
            int n = wn + nt * 8 + g;                                            \
            tf32_split_u((sB)[(kk + tg) * BPAD + n],     bhi[nt][0], blo[nt][0]); \
            tf32_split_u((sB)[(kk + tg + 4) * BPAD + n], bhi[nt][1], blo[nt][1]); \
        }                                                                       \
        _Pragma("unroll")                                                       \
        for (int mt = 0; mt < 2; mt++)                                          \
            _Pragma("unroll")                                                   \
            for (int nt = 0; nt < 4; nt++) {                                    \
                MMA_TF32(acc[mt][nt], ahi[mt], bhi[nt]);                        \
                MMA_TF32(acc[mt][nt], ahi[mt], blo[nt]);                        \
                MMA_TF32(acc[mt][nt], alo[mt], bhi[nt]);                        \
            }                                                                   \
    }

// ---------------- generic GEMM (init): C[M,128] = A[M,K]@W + bias, M-tile 64 ---
__global__ __launch_bounds__(256) void gemm64(
    const float* __restrict__ Ap, int lda,
    const float* __restrict__ Wp, const float* __restrict__ bias,
    float* __restrict__ Cp, int M, int K)
{
    __shared__ __align__(16) float sA[2][64 * APAD];
    __shared__ __align__(16) float sB[2][16 * BPAD];
    int t = threadIdx.x, lane = t & 31, w = t >> 5;
    int wm = (w & 1) * 32, wn = (w >> 1) * 32;
    int g = lane >> 2, tg = lane & 3;
    int m0 = blockIdx.x * 64;
    int arow = t >> 2, akq = t & 3;
    int bkr = t >> 4, bn4 = (t & 15) * 8;
    int gm = m0 + arow;
    float acc[2][4][4];
#pragma unroll
    for (int a = 0; a < 2; a++)
#pragma unroll
        for (int b = 0; b < 4; b++)
#pragma unroll
            for (int c = 0; c < 4; c++) acc[a][b][c] = 0.f;

    float4 va = make_float4(0.f, 0.f, 0.f, 0.f);
    if (gm < M) va = *(const float4*)(Ap + (size_t)gm * lda + akq * 4);
    float4 vb0 = *(const float4*)(Wp + (size_t)bkr * 128 + bn4);
    float4 vb1 = *(const float4*)(Wp + (size_t)bkr * 128 + bn4 + 4);
    *(float4*)&sA[0][arow * APAD + akq * 4] = va;
    *(float4*)&sB[0][bkr * BPAD + bn4]      = vb0;
    *(float4*)&sB[0][bkr * BPAD + bn4 + 4]  = vb1;
    __syncthreads();

    int p = 0;
    for (int k0 = 0; k0 < K; k0 += 16) {
        int kn = k0 + 16;
        if (kn < K) {
            va = make_float4(0.f, 0.f, 0.f, 0.f);
            if (gm < M) va = *(const float4*)(Ap + (size_t)gm * lda + kn + akq * 4);
            vb0 = *(const float4*)(Wp + (size_t)(kn + bkr) * 128 + bn4);
            vb1 = *(const float4*)(Wp + (size_t)(kn + bkr) * 128 + bn4 + 4);
        }
        MMA_SLAB(sA[p], sB[p], acc)
        if (kn < K) {
            *(float4*)&sA[p ^ 1][arow * APAD + akq * 4] = va;
            *(float4*)&sB[p ^ 1][bkr * BPAD + bn4]      = vb0;
            *(float4*)&sB[p ^ 1][bkr * BPAD + bn4 + 4]  = vb1;
            __syncthreads();
            p ^= 1;
        }
    }
#pragma unroll
    for (int mt = 0; mt < 2; mt++) {
        int r0 = m0 + wm + mt * 16 + g;
#pragma unroll
        for (int nt = 0; nt < 4; nt++) {
            int c = wn + nt * 8 + 2 * tg;
            float b0 = bias ? bias[c] : 0.f;
            float b1 = bias ? bias[c + 1] : 0.f;
            if (r0 < M) {
                Cp[(size_t)r0 * 128 + c]     = acc[mt][nt][0] + b0;
                Cp[(size_t)r0 * 128 + c + 1] = acc[mt][nt][1] + b1;
            }
            if (r0 + 8 < M) {
                Cp[(size_t)(r0 + 8) * 128 + c]     = acc[mt][nt][2] + b0;
                Cp[(size_t)(r0 + 8) * 128 + c + 1] = acc[mt][nt][3] + b1;
            }
        }
    }
}

// ------- fused node GEMMs: y=0: A=h@W1a, y=1: B=h@W1b, y=2: U=h@nodeW+node_b ---
__global__ __launch_bounds__(256) void gemm_h3(
    const float* __restrict__ Wa, const float* __restrict__ Wb,
    const float* __restrict__ Wn, const float* __restrict__ nodeB, int M)
{
    __shared__ __align__(16) float sA[2][64 * APAD];
    __shared__ __align__(16) float sB[2][16 * BPAD];
    int y = blockIdx.y;
    const float* Wp = (y == 0) ? Wa : ((y == 1) ? Wb : Wn);
    float* Cp = (y == 0) ? g_Ab : ((y == 1) ? g_Bb : g_U);
    const float* bias = (y == 2) ? nodeB : 0;

    int t = threadIdx.x, lane = t & 31, w = t >> 5;
    int wm = (w & 1) * 32, wn = (w >> 1) * 32;
    int g = lane >> 2, tg = lane & 3;
    int m0 = blockIdx.x * 64;
    int arow = t >> 2, akq = t & 3;
    int bkr = t >> 4, bn4 = (t & 15) * 8;
    int gm = m0 + arow;
    float acc[2][4][4];
#pragma unroll
    for (int a = 0; a < 2; a++)
#pragma unroll
        for (int b = 0; b < 4; b++)
#pragma unroll
            for (int c = 0; c < 4; c++) acc[a][b][c] = 0.f;

    float4 va = make_float4(0.f, 0.f, 0.f, 0.f);
    if (gm < M) va = *(const float4*)(g_h + (size_t)gm * 128 + akq * 4);
    float4 vb0 = *(const float4*)(Wp + (size_t)bkr * 128 + bn4);
    float4 vb1 = *(const float4*)(Wp + (size_t)bkr * 128 + bn4 + 4);
    *(float4*)&sA[0][arow * APAD + akq * 4] = va;
    *(float4*)&sB[0][bkr * BPAD + bn4]      = vb0;
    *(float4*)&sB[0][bkr * BPAD + bn4 + 4]  = vb1;
    __syncthreads();

    int p = 0;
    for (int k0 = 0; k0 < 128; k0 += 16) {
        int kn = k0 + 16;
        if (kn < 128) {
            va = make_float4(0.f, 0.f, 0.f, 0.f);
            if (gm < M) va = *(const float4*)(g_h + (size_t)gm * 128 + kn + akq * 4);
            vb0 = *(const float4*)(Wp + (size_t)(kn + bkr) * 128 + bn4);
            vb1 = *(const float4*)(Wp + (size_t)(kn + bkr) * 128 + bn4 + 4);
        }
        MMA_SLAB(sA[p], sB[p], acc)
        if (kn < 128) {
            *(float4*)&sA[p ^ 1][arow * APAD + akq * 4] = va;
            *(float4*)&sB[p ^ 1][bkr * BPAD + bn4]      = vb0;
            *(float4*)&sB[p ^ 1][bkr * BPAD + bn4 + 4]  = vb1;
            __syncthreads();
            p ^= 1;
        }
    }
#pragma unroll
    for (int mt = 0; mt < 2; mt++) {
        int r0 = m0 + wm + mt * 16 + g;
#pragma unroll
        for (int nt = 0; nt < 4; nt++) {
            int c = wn + nt * 8 + 2 * tg;
            float b0 = bias ? bias[c] : 0.f;
            float b1 = bias ? bias[c + 1] : 0.f;
            if (r0 < M) {
                Cp[(size_t)r0 * 128 + c]     = acc[mt][nt][0] + b0;
                Cp[(size_t)r0 * 128 + c + 1] = acc[mt][nt][1] + b1;
            }
            if (r0 + 8 < M) {
                Cp[(size_t)(r0 + 8) * 128 + c]     = acc[mt][nt][2] + b0;
                Cp[(size_t)(r0 + 8) * 128 + c + 1] = acc[mt][nt][3] + b1;
            }
        }
    }
}

// ------- fused edge pass: GEMM(ea@W1c) + gather A/B/relpos + BN/ReLU + scatter --
__global__ __launch_bounds__(256) void edge_fused(
    const float* __restrict__ ea, const float* __restrict__ pos,
    const float* __restrict__ W1,
    const float* __restrict__ gn, const float* __restrict__ be,
    const float* __restrict__ b1, int E)
{
    __shared__ __align__(16) float sA[2][64 * APAD];
    __shared__ __align__(16) float sB[2][16 * BPAD];
    __shared__ __align__(16) float stage[64 * SPAD];
    __shared__ __align__(16) float w1d[3 * 128];
    __shared__ __align__(16) float sc[128], sh[128];
    __shared__ float srp[64 * 3];
    __shared__ int   sdst[64], ssrc[64];

    int t = threadIdx.x, lane = t & 31, w = t >> 5;
    int wm = (w & 1) * 32, wn = (w >> 1) * 32;
    int g = lane >> 2, tg = lane & 3;
    int m0 = blockIdx.x * 64;

    if (t < 128) {
        float s = gn[t] * rsqrtf(1.0f + EPSBN);
        sc[t] = s;
        sh[t] = fmaf(b1[t], s, be[t]);
        w1d[t]       = W1[320 * 128 + t];
        w1d[128 + t] = W1[321 * 128 + t];
        w1d[256 + t] = W1[322 * 128 + t];
    }
    if (t < 64) {
        int e = m0 + t;
        int s = 0, d = 0;
        float r0 = 0.f, r1 = 0.f, r2 = 0.f;
        if (e < E) {
            s = g_src[e]; d = g_dst[e];
            r0 = pos[d * 3 + 0] - pos[s * 3 + 0];
            r1 = pos[d * 3 + 1] - pos[s * 3 + 1];
            r2 = pos[d * 3 + 2] - pos[s * 3 + 2];
        }
        ssrc[t] = s; sdst[t] = d;
        srp[t * 3 + 0] = r0; srp[t * 3 + 1] = r1; srp[t * 3 + 2] = r2;
    }

    const float* Wc = W1 + 256 * 128;
    int arow = t >> 2, akq = t & 3;
    int bkr = t >> 4, bn4 = (t & 15) * 8;
    int ge = m0 + arow;
    float acc[2][4][4];
#pragma unroll
    for (int a = 0; a < 2; a++)
#pragma unroll
        for (int b = 0; b < 4; b++)
#pragma unroll
            for (int c = 0; c < 4; c++) acc[a][b][c] = 0.f;

    float4 va = make_float4(0.f, 0.f, 0.f, 0.f);
    if (ge < E) va = *(const float4*)(ea + (size_t)ge * 64 + akq * 4);
    float4 vb0 = *(const float4*)(Wc + (size_t)bkr * 128 + bn4);
    float4 vb1 = *(const float4*)(Wc + (size_t)bkr * 128 + bn4 + 4);
    *(float4*)&sA[0][arow * APAD + akq * 4] = va;
    *(float4*)&sB[0][bkr * BPAD + bn4]      = vb0;
    *(float4*)&sB[0][bkr * BPAD + bn4 + 4]  = vb1;
    __syncthreads();

    int p = 0;
    for (int k0 = 0; k0 < 64; k0 += 16) {
        int kn = k0 + 16;
        if (kn < 64) {
            va = make_float4(0.f, 0.f, 0.f, 0.f);
            if (ge < E) va = *(const float4*)(ea + (size_t)ge * 64 + kn + akq * 4);
            vb0 = *(const float4*)(Wc + (size_t)(kn + bkr) * 128 + bn4);
            vb1 = *(const float4*)(Wc + (size_t)(kn + bkr) * 128 + bn4 + 4);
        }
        MMA_SLAB(sA[p], sB[p], acc)
        if (kn < 64) {
            *(float4*)&sA[p ^ 1][arow * APAD + akq * 4] = va;
            *(float4*)&sB[p ^ 1][bkr * BPAD + bn4]      = vb0;
            *(float4*)&sB[p ^ 1][bkr * BPAD + bn4 + 4]  = vb1;
            __syncthreads();
            p ^= 1;
        }
    }
    __syncthreads();

    // single staging pass: every warp writes its (row,col) patch; one sync
#pragma unroll
    for (int mt = 0; mt < 2; mt++)
#pragma unroll
        for (int nt = 0; nt < 4; nt++)
#pragma unroll
            for (int half = 0; half < 2; half++) {
                int el = wm + mt * 16 + g + half * 8;   // 0..63
                int c = wn + nt * 8 + 2 * tg;
                stage[el * SPAD + c]     = acc[mt][nt][half * 2 + 0];
                stage[el * SPAD + c + 1] = acc[mt][nt][half * 2 + 1];
            }
    __syncthreads();

    // scatter: each warp handles 8 independent edges (deep MLP)
    {
        int j = lane * 4;
        float4 scv = *(const float4*)&sc[j];
        float4 shv = *(const float4*)&sh[j];
        float4 w0 = *(const float4*)&w1d[j];
        float4 w1v = *(const float4*)&w1d[128 + j];
        float4 w2 = *(const float4*)&w1d[256 + j];
#pragma unroll
        for (int i = 0; i < 8; i++) {
            int el = w * 8 + i;                 // 0..63
            int eg = m0 + el;
            if (eg < E) {
                int d = sdst[el], s2 = ssrc[el];
                float rp0 = srp[el * 3 + 0];
                float rp1 = srp[el * 3 + 1];
                float rp2 = srp[el * 3 + 2];
                float4 cv = *(const float4*)&stage[el * SPAD + j];
                float4 av = *(const float4*)&g_Ab[(size_t)d * 128 + j];
                float4 bv = *(const float4*)&g_Bb[(size_t)s2 * 128 + j];
                float m0v = cv.x + av.x + bv.x + rp0 * w0.x + rp1 * w1v.x + rp2 * w2.x;
                float m1v = cv.y + av.y + bv.y + rp0 * w0.y + rp1 * w1v.y + rp2 * w2.y;
                float m2v = cv.z + av.z + bv.z + rp0 * w0.z + rp1 * w1v.z + rp2 * w2.z;
                float m3v = cv.w + av.w + bv.w + rp0 * w0.w + rp1 * w1v.w + rp2 * w2.w;
                float r0 = fmaxf(fmaf(m0v, scv.x, shv.x), 0.f);
                float r1 = fmaxf(fmaf(m1v, scv.y, shv.y), 0.f);
                float r2 = fmaxf(fmaf(m2v, scv.z, shv.z), 0.f);
                float r3 = fmaxf(fmaf(m3v, scv.w, shv.w), 0.f);
                float* pS = &g_S[(size_t)d * 128 + j];
                asm volatile("red.global.add.v4.f32 [%0], {%1, %2, %3, %4};"
                             :: "l"(pS), "f"(r0), "f"(r1), "f"(r2), "f"(r3) : "memory");
            }
        }
    }
}

// ------- node update: h += relu( U + (S + selfmsg)@W2 + deg*b2 ) ---------------
__global__ __launch_bounds__(256) void node1(
    const float* __restrict__ W2, const float* __restrict__ b2,
    const float* __restrict__ gn, const float* __restrict__ be,
    const float* __restrict__ b1, int M)
{
    __shared__ __align__(16) float sA[2][64 * APAD];
    __shared__ __align__(16) float sB[2][16 * BPAD];
    __shared__ float sc[128], sh[128], b2s[128];
    int t = threadIdx.x, lane = t & 31, w = t >> 5;
    if (t < 128) {
        float s = gn[t] * rsqrtf(1.0f + EPSBN);
        sc[t] = s;
        sh[t] = fmaf(b1[t], s, be[t]);
        b2s[t] = b2[t];
    }
    __syncthreads();
    int wm = (w & 1) * 32, wn = (w >> 1) * 32;
    int g = lane >> 2, tg = lane & 3;
    int m0 = blockIdx.x * 64;
    int arow = t >> 2, akq = t & 3;
    int bkr = t >> 4, bn4 = (t & 15) * 8;
    int gm = m0 + arow;
    float acc[2][4][4];
#pragma unroll
    for (int a = 0; a < 2; a++)
#pragma unroll
        for (int b = 0; b < 4; b++)
#pragma unroll
            for (int c = 0; c < 4; c++) acc[a][b][c] = 0.f;

    // prefetch raw vectors for k=0 and build first A tile
    float4 pv_s = make_float4(0.f, 0.f, 0.f, 0.f);
    float4 pv_a = pv_s, pv_b = pv_s;
    if (gm < M) {
        pv_s = *(const float4*)(g_S  + (size_t)gm * 128 + akq * 4);
        pv_a = *(const float4*)(g_Ab + (size_t)gm * 128 + akq * 4);
        pv_b = *(const float4*)(g_Bb + (size_t)gm * 128 + akq * 4);
    }
    float4 vb0 = *(const float4*)(W2 + (size_t)bkr * 128 + bn4);
    float4 vb1 = *(const float4*)(W2 + (size_t)bkr * 128 + bn4 + 4);
    {
        float4 out;
        float* sp = (float*)&pv_s; float* ap = (float*)&pv_a;
        float* bp = (float*)&pv_b; float* op = (float*)&out;
#pragma unroll
        for (int j = 0; j < 4; j++) {
            int k = akq * 4 + j;
            float r = fmaxf(fmaf(ap[j] + bp[j], sc[k], sh[k]), 0.f);
            op[j] = sp[j] + r;
        }
        *(float4*)&sA[0][arow * APAD + akq * 4] = out;
    }
    *(float4*)&sB[0][bkr * BPAD + bn4]     = vb0;
    *(float4*)&sB[0][bkr * BPAD + bn4 + 4] = vb1;
    __syncthreads();

    int p = 0;
    for (int k0 = 0; k0 < 128; k0 += 16) {
        int kn = k0 + 16;
        if (kn < 128) {
            pv_s = make_float4(0.f, 0.f, 0.f, 0.f);
            pv_a = pv_s; pv_b = pv_s;
            if (gm < M) {
                pv_s = *(const float4*)(g_S  + (size_t)gm * 128 + kn + akq * 4);
                pv_a = *(const float4*)(g_Ab + (size_t)gm * 128 + kn + akq * 4);
                pv_b = *(const float4*)(g_Bb + (size_t)gm * 128 + kn + akq * 4);
            }
            vb0 = *(const float4*)(W2 + (size_t)(kn + bkr) * 128 + bn4);
            vb1 = *(const float4*)(W2 + (size_t)(kn + bkr) * 128 + bn4 + 4);
        }
        MMA_SLAB(sA[p], sB[p], acc)
        if (kn < 128) {
            float4 out;
            float* sp = (float*)&pv_s; float* ap = (float*)&pv_a;
            float* bp = (float*)&pv_b; float* op = (float*)&out;
#pragma unroll
            for (int j = 0; j < 4; j++) {
                int k = kn + akq * 4 + j;
                float r = fmaxf(fmaf(ap[j] + bp[j], sc[k], sh[k]), 0.f);
                op[j] = sp[j] + r;
            }
            *(float4*)&sA[p ^ 1][arow * APAD + akq * 4] = out;
            *(float4*)&sB[p ^ 1][bkr * BPAD + bn4]     = vb0;
            *(float4*)&sB[p ^ 1][bkr * BPAD + bn4 + 4] = vb1;
            __syncthreads();
            p ^= 1;
        }
    }
#pragma unroll
    for (int mt = 0; mt < 2; mt++) {
        int r0 = m0 + wm + mt * 16 + g;
#pragma unroll
        for (int nt = 0; nt < 4; nt++) {
            int c = wn + nt * 8 + 2 * tg;
#pragma unroll
            for (int half = 0; half < 2; half++) {
                int rr = r0 + half * 8;
                if (rr < M) {
                    float dg = g_deg[rr];
                    float u0 = g_U[(size_t)rr * 128 + c];
                    float u1 = g_U[(size_t)rr * 128 + c + 1];
                    float v0 = acc[mt][nt][half * 2 + 0] + u0 + dg * b2s[c];
                    float v1 = acc[mt][nt][half * 2 + 1] + u1 + dg * b2s[c + 1];
                    g_h[(size_t)rr * 128 + c]     += fmaxf(v0, 0.f);
                    g_h[(size_t)rr * 128 + c + 1] += fmaxf(v1, 0.f);
                }
            }
        }
    }
}

// ---------------- pooling + output MLP ------------------------------------------
__global__ void pool_kernel(int N) {
    int w = (blockIdx.x * blockDim.x + threadIdx.x) >> 5;
    int lane = threadIdx.x & 31;
    if (w >= N) return;
    int gph = g_batch[w];
    int j = lane * 4;
    float4 v = *(const float4*)&g_h[(size_t)w * 128 + j];
    float* p = &g_P[(size_t)gph * 128 + j];
    asm volatile("red.global.add.v4.f32 [%0], {%1, %2, %3, %4};"
                 :: "l"(p), "f"(v.x), "f"(v.y), "f"(v.z), "f"(v.w) : "memory");
    if (lane == 0) atomicAdd(&g_cnt[gph], 1.0f);
}

__global__ void head_kernel(
    const float* __restrict__ W1, const float* __restrict__ b1,
    const float* __restrict__ gn, const float* __restrict__ be,
    const float* __restrict__ W2, const float* __restrict__ b2,
    float* __restrict__ out)
{
    __shared__ float pl[128], o1[128];
    int gph = blockIdx.x;
    int t = threadIdx.x;
    float c = fmaxf(g_cnt[gph], 1.0f);
    pl[t] = g_P[gph * 128 + t] / c;
    __syncthreads();
    float acc = b1[t];
    for (int k = 0; k < 128; k++) acc = fmaf(pl[k], W1[k * 128 + t], acc);
    float s = gn[t] * rsqrtf(1.0f + EPSBN);
    o1[t] = fmaxf(fmaf(acc, s, be[t]), 0.f);
    __syncthreads();
    float acc2 = b2[t];
    for (int k = 0; k < 128; k++) acc2 = fmaf(o1[k], W2[k * 128 + t], acc2);
    out[gph * 128 + t] = acc2;
}

// ---------------- launch ---------------------------------------------------------
extern "C" void kernel_launch(void* const* d_in, const int* in_sizes, int n_in,
                              void* d_out, int out_size)
{
    const float* x       = (const float*)d_in[0];
    const void*  ei      = d_in[1];
    const float* ea      = (const float*)d_in[2];
    const float* pos     = (const float*)d_in[3];
    const void*  bt      = d_in[4];
    const float* Wi      = (const float*)d_in[5];
    const float* bi      = (const float*)d_in[6];
    const float* node_W  = (const float*)d_in[7];
    const float* node_b  = (const float*)d_in[8];
    const float* msg_W1  = (const float*)d_in[9];
    const float* msg_b1  = (const float*)d_in[10];
    const float* msg_g   = (const float*)d_in[11];
    const float* msg_be  = (const float*)d_in[12];
    const float* msg_W2  = (const float*)d_in[13];
    const float* msg_b2  = (const float*)d_in[14];
    const float* out_W1  = (const float*)d_in[15];
    const float* out_b1  = (const float*)d_in[16];
    const float* out_g   = (const float*)d_in[17];
    const float* out_be  = (const float*)d_in[18];
    const float* out_W2  = (const float*)d_in[19];
    const float* out_b2  = (const float*)d_in[20];

    int N = in_sizes[3] / 3;   // pos [N,3]
    int E = in_sizes[1] / 2;   // edge_index [2,E]

    void *hp, *Sp, *Pp, *cp;
    cudaGetSymbolAddress(&hp, g_h);
    cudaGetSymbolAddress(&Sp, g_S);
    cudaGetSymbolAddress(&Pp, g_P);
    cudaGetSymbolAddress(&cp, g_cnt);

    detect_kernel<<<1, 256>>>(ei, bt, N, E);
    int mx = (N > E ? N : E);
    convert_kernel<<<(mx + 255) / 256, 256>>>(ei, bt, N, E);
    deg_kernel<<<(E + 255) / 256, 256>>>(E);

    int nT = (N + 63) / 64;
    int eT = (E + 63) / 64;

    // h = x @ Wi + bi
    gemm64<<<nT, 256>>>(x, 256, Wi, bi, (float*)hp, N, 256);

    for (int l = 0; l < 3; l++) {
        const float* W1l = msg_W1 + (size_t)l * 323 * 128;
        // A = h@W1a, B = h@W1b, U = h@nodeW + node_b (one fused launch)
        gemm_h3<<<dim3(nT, 3), 256>>>(W1l, W1l + 128 * 128,
                                      node_W + (size_t)l * 128 * 128,
                                      node_b + l * 128, N);
        cudaMemsetAsync(Sp, 0, (size_t)N * 128 * sizeof(float));
        edge_fused<<<eT, 256>>>(ea, pos, W1l,
                                msg_g + l * 128, msg_be + l * 128,
                                msg_b1 + l * 128, E);
        node1<<<nT, 256>>>(msg_W2 + (size_t)l * 128 * 128, msg_b2 + l * 128,
                           msg_g + l * 128, msg_be + l * 128,
                           msg_b1 + l * 128, N);
    }

    cudaMemsetAsync(Pp, 0, GG * 128 * sizeof(float));
    cudaMemsetAsync(cp, 0, GG * sizeof(float));
    pool_kernel<<<(N * 32 + 255) / 256, 256>>>(N);
    head_kernel<<<GG, 128>>>(out_W1, out_b1, out_g, out_be, out_W2, out_b2,
                             (float*)d_out);
}

// round 14
// speedup vs baseline: 1.1197x; 1.0000x over previous
#include <cuda_runtime.h>
#include <math.h>

#define NN 50000
#define EE 400000
#define GG 64
#define EPSBN 1e-5f
#define APAD 20    // A tile row stride (floats)
#define BPAD 136   // B tile row stride (floats)
#define SPAD 132   // staging tile row stride

// ---------------- scratch ------------------------------------------------------
__device__ float g_h[NN * 128];
__device__ float g_Ab[NN * 128];
__device__ float g_Bb[NN * 128];
__device__ float g_U[NN * 128];
__device__ float g_S[NN * 128];
__device__ int   g_src[EE];
__device__ int   g_dst[EE];
__device__ int   g_batch[NN];
__device__ float g_deg[NN];
__device__ float g_P[GG * 128];
__device__ float g_cnt[GG];
__device__ int   g_e64;
__device__ int   g_b64;

// ---------------- dtype detection ----------------------------------------------
__global__ void detect_kernel(const void* ei, const void* bt, int N, int E) {
    __shared__ int s_e, s_b;
    int t = threadIdx.x;
    if (t == 0) { s_e = 1; s_b = 1; }
    __syncthreads();
    const long long* p = (const long long*)ei;
    long long v = p[t];
    if (v < 0 || v >= (long long)N) s_e = 0;
    int base = N / 2 - 256; if (base < 0) base = 0;
    const long long* q = (const long long*)bt;
    long long w = q[base + t];
    if (w < 0 || w >= (long long)GG) s_b = 0;
    __syncthreads();
    if (t == 0) { g_e64 = s_e; g_b64 = s_b; }
}

__global__ void convert_kernel(const void* ei, const void* bt, int N, int E) {
    int i = blockIdx.x * blockDim.x + threadIdx.x;
    int e64 = g_e64, b64 = g_b64;
    if (i < E) {
        if (e64) {
            const long long* p = (const long long*)ei;
            g_src[i] = (int)p[i];
            g_dst[i] = (int)p[E + i];
        } else {
            const int* p = (const int*)ei;
            g_src[i] = p[i];
            g_dst[i] = p[E + i];
        }
    }
    if (i < N) {
        if (b64) g_batch[i] = (int)((const long long*)bt)[i];
        else     g_batch[i] = ((const int*)bt)[i];
        g_deg[i] = 1.0f;   // self loop
    }
}

__global__ void deg_kernel(int E) {
    int i = blockIdx.x * blockDim.x + threadIdx.x;
    if (i < E) atomicAdd(&g_deg[g_dst[i]], 1.0f);
}

// ---------------- tf32 helpers --------------------------------------------------
__device__ __forceinline__ void tf32_split_u(float v, unsigned& hi, unsigned& lo) {
    asm("cvt.rna.tf32.f32 %0, %1;" : "=r"(hi) : "f"(v));
    float l = v - __uint_as_float(hi);
    asm("cvt.rna.tf32.f32 %0, %1;" : "=r"(lo) : "f"(l));
}

#define MMA_TF32(d, a, b)                                              \
    asm volatile("mma.sync.aligned.m16n8k8.row.col.f32.tf32.tf32.f32 " \
        "{%0,%1,%2,%3}, {%4,%5,%6,%7}, {%8,%9}, {%0,%1,%2,%3};"        \
        : "+f"((d)[0]), "+f"((d)[1]), "+f"((d)[2]), "+f"((d)[3])       \
        : "r"((a)[0]), "r"((a)[1]), "r"((a)[2]), "r"((a)[3]),          \
          "r"((b)[0]), "r"((b)[1]))

// fragment-load (fp32 smem) + in-register split + 3xTF32 MMA, M64xN128 tiling
#define MMA_SLAB(sA, sB, acc)                                                   \
    _Pragma("unroll")                                                           \
    for (int kk = 0; kk < 16; kk += 8) {                                        \
        unsigned ahi[2][4], alo[2][4], bhi[4][2], blo[4][2];                    \
        _Pragma("unroll")                                                       \
        for (int mt = 0; mt < 2; mt++) {                                        \
            int base = (wm + mt * 16 + g) * APAD + kk + tg;                     \
            tf32_split_u((sA)[base],                ahi[mt][0], alo[mt][0]);    \
            tf32_split_u((sA)[base + 8 * APAD],     ahi[mt][1], alo[mt][1]);    \
            tf32_split_u((sA)[base + 4],            ahi[mt][2], alo[mt][2]);    \
            tf32_split_u((sA)[base + 8 * APAD + 4], ahi[mt][3], alo[mt][3]);    \
        }                                                                       \
        _Pragma("unroll")                                                       \
        for (int nt = 0; nt < 4; nt++) {                                        \
            int n = wn + nt * 8 + g;                                            \
            tf32_split_u((sB)[(kk + tg) * BPAD + n],     bhi[nt][0], blo[nt][0]); \
            tf32_split_u((sB)[(kk + tg + 4) * BPAD + n], bhi[nt][1], blo[nt][1]); \
        }                                                                       \
        _Pragma("unroll")                                                       \
        for (int mt = 0; mt < 2; mt++)                                          \
            _Pragma("unroll")                                                   \
            for (int nt = 0; nt < 4; nt++) {                                    \
                MMA_TF32(acc[mt][nt], ahi[mt], bhi[nt]);                        \
                MMA_TF32(acc[mt][nt], ahi[mt], blo[nt]);                        \
                MMA_TF32(acc[mt][nt], alo[mt], bhi[nt]);                        \
            }                                                                   \
    }

// ---------------- generic GEMM (init): C[M,128] = A[M,K]@W + bias, M-tile 64 ---
__global__ __launch_bounds__(256, 3) void gemm64(
    const float* __restrict__ Ap, int lda,
    const float* __restrict__ Wp, const float* __restrict__ bias,
    float* __restrict__ Cp, int M, int K)
{
    __shared__ __align__(16) float sA[64 * APAD];
    __shared__ __align__(16) float sB[16 * BPAD];
    int t = threadIdx.x, lane = t & 31, w = t >> 5;
    int wm = (w & 1) * 32, wn = (w >> 1) * 32;
    int g = lane >> 2, tg = lane & 3;
    int m0 = blockIdx.x * 64;
    int arow = t >> 2, akq = t & 3;
    int bkr = t >> 4, bn4 = (t & 15) * 8;
    int gm = m0 + arow;
    float acc[2][4][4];
#pragma unroll
    for (int a = 0; a < 2; a++)
#pragma unroll
        for (int b = 0; b < 4; b++)
#pragma unroll
            for (int c = 0; c < 4; c++) acc[a][b][c] = 0.f;

    float4 va = make_float4(0.f, 0.f, 0.f, 0.f);
    if (gm < M) va = *(const float4*)(Ap + (size_t)gm * lda + akq * 4);
    float4 vb0 = *(const float4*)(Wp + (size_t)bkr * 128 + bn4);
    float4 vb1 = *(const float4*)(Wp + (size_t)bkr * 128 + bn4 + 4);

    for (int k0 = 0; k0 < K; k0 += 16) {
        *(float4*)&sA[arow * APAD + akq * 4] = va;
        *(float4*)&sB[bkr * BPAD + bn4]      = vb0;
        *(float4*)&sB[bkr * BPAD + bn4 + 4]  = vb1;
        __syncthreads();
        int kn = k0 + 16;
        if (kn < K) {
            va = make_float4(0.f, 0.f, 0.f, 0.f);
            if (gm < M) va = *(const float4*)(Ap + (size_t)gm * lda + kn + akq * 4);
            vb0 = *(const float4*)(Wp + (size_t)(kn + bkr) * 128 + bn4);
            vb1 = *(const float4*)(Wp + (size_t)(kn + bkr) * 128 + bn4 + 4);
        }
        MMA_SLAB(sA, sB, acc)
        __syncthreads();
    }
#pragma unroll
    for (int mt = 0; mt < 2; mt++) {
        int r0 = m0 + wm + mt * 16 + g;
#pragma unroll
        for (int nt = 0; nt < 4; nt++) {
            int c = wn + nt * 8 + 2 * tg;
            float b0 = bias ? bias[c] : 0.f;
            float b1 = bias ? bias[c + 1] : 0.f;
            if (r0 < M) {
                Cp[(size_t)r0 * 128 + c]     = acc[mt][nt][0] + b0;
                Cp[(size_t)r0 * 128 + c + 1] = acc[mt][nt][1] + b1;
            }
            if (r0 + 8 < M) {
                Cp[(size_t)(r0 + 8) * 128 + c]     = acc[mt][nt][2] + b0;
                Cp[(size_t)(r0 + 8) * 128 + c + 1] = acc[mt][nt][3] + b1;
            }
        }
    }
}

// ------- fused node GEMMs: y=0: A=h@W1a, y=1: B=h@W1b, y=2: U=h@nodeW+node_b ---
__global__ __launch_bounds__(256, 3) void gemm_h3(
    const float* __restrict__ Wa, const float* __restrict__ Wb,
    const float* __restrict__ Wn, const float* __restrict__ nodeB, int M)
{
    __shared__ __align__(16) float sA[64 * APAD];
    __shared__ __align__(16) float sB[16 * BPAD];
    int y = blockIdx.y;
    const float* Wp = (y == 0) ? Wa : ((y == 1) ? Wb : Wn);
    float* Cp = (y == 0) ? g_Ab : ((y == 1) ? g_Bb : g_U);
    const float* bias = (y == 2) ? nodeB : 0;

    int t = threadIdx.x, lane = t & 31, w = t >> 5;
    int wm = (w & 1) * 32, wn = (w >> 1) * 32;
    int g = lane >> 2, tg = lane & 3;
    int m0 = blockIdx.x * 64;
    int arow = t >> 2, akq = t & 3;
    int bkr = t >> 4, bn4 = (t & 15) * 8;
    int gm = m0 + arow;
    float acc[2][4][4];
#pragma unroll
    for (int a = 0; a < 2; a++)
#pragma unroll
        for (int b = 0; b < 4; b++)
#pragma unroll
            for (int c = 0; c < 4; c++) acc[a][b][c] = 0.f;

    float4 va = make_float4(0.f, 0.f, 0.f, 0.f);
    if (gm < M) va = *(const float4*)(g_h + (size_t)gm * 128 + akq * 4);
    float4 vb0 = *(const float4*)(Wp + (size_t)bkr * 128 + bn4);
    float4 vb1 = *(const float4*)(Wp + (size_t)bkr * 128 + bn4 + 4);

    for (int k0 = 0; k0 < 128; k0 += 16) {
        *(float4*)&sA[arow * APAD + akq * 4] = va;
        *(float4*)&sB[bkr * BPAD + bn4]      = vb0;
        *(float4*)&sB[bkr * BPAD + bn4 + 4]  = vb1;
        __syncthreads();
        int kn = k0 + 16;
        if (kn < 128) {
            va = make_float4(0.f, 0.f, 0.f, 0.f);
            if (gm < M) va = *(const float4*)(g_h + (size_t)gm * 128 + kn + akq * 4);
            vb0 = *(const float4*)(Wp + (size_t)(kn + bkr) * 128 + bn4);
            vb1 = *(const float4*)(Wp + (size_t)(kn + bkr) * 128 + bn4 + 4);
        }
        MMA_SLAB(sA, sB, acc)
        __syncthreads();
    }
#pragma unroll
    for (int mt = 0; mt < 2; mt++) {
        int r0 = m0 + wm + mt * 16 + g;
#pragma unroll
        for (int nt = 0; nt < 4; nt++) {
            int c = wn + nt * 8 + 2 * tg;
            float b0 = bias ? bias[c] : 0.f;
            float b1 = bias ? bias[c + 1] : 0.f;
            if (r0 < M) {
                Cp[(size_t)r0 * 128 + c]     = acc[mt][nt][0] + b0;
                Cp[(size_t)r0 * 128 + c + 1] = acc[mt][nt][1] + b1;
            }
            if (r0 + 8 < M) {
                Cp[(size_t)(r0 + 8) * 128 + c]     = acc[mt][nt][2] + b0;
                Cp[(size_t)(r0 + 8) * 128 + c + 1] = acc[mt][nt][3] + b1;
            }
        }
    }
}

// ------- fused edge pass: GEMM(ea@W1c) + gather A/B/relpos + BN/ReLU + scatter --
__global__ __launch_bounds__(256, 2) void edge_fused(
    const float* __restrict__ ea, const float* __restrict__ pos,
    const float* __restrict__ W1,
    const float* __restrict__ gn, const float* __restrict__ be,
    const float* __restrict__ b1, int E)
{
    __shared__ __align__(16) float sA[64 * APAD];
    __shared__ __align__(16) float sB[16 * BPAD];
    __shared__ __align__(16) float stage[64 * SPAD];
    __shared__ __align__(16) float w1d[3 * 128];
    __shared__ __align__(16) float sc[128], sh[128];
    __shared__ float srp[64 * 3];
    __shared__ int   sdst[64], ssrc[64];

    int t = threadIdx.x, lane = t & 31, w = t >> 5;
    int wm = (w & 1) * 32, wn = (w >> 1) * 32;
    int g = lane >> 2, tg = lane & 3;
    int m0 = blockIdx.x * 64;

    if (t < 128) {
        float s = gn[t] * rsqrtf(1.0f + EPSBN);
        sc[t] = s;
        sh[t] = fmaf(b1[t], s, be[t]);
        w1d[t]       = W1[320 * 128 + t];
        w1d[128 + t] = W1[321 * 128 + t];
        w1d[256 + t] = W1[322 * 128 + t];
    }
    if (t < 64) {
        int e = m0 + t;
        int s = 0, d = 0;
        float r0 = 0.f, r1 = 0.f, r2 = 0.f;
        if (e < E) {
            s = g_src[e]; d = g_dst[e];
            r0 = pos[d * 3 + 0] - pos[s * 3 + 0];
            r1 = pos[d * 3 + 1] - pos[s * 3 + 1];
            r2 = pos[d * 3 + 2] - pos[s * 3 + 2];
        }
        ssrc[t] = s; sdst[t] = d;
        srp[t * 3 + 0] = r0; srp[t * 3 + 1] = r1; srp[t * 3 + 2] = r2;
    }

    const float* Wc = W1 + 256 * 128;
    int arow = t >> 2, akq = t & 3;
    int bkr = t >> 4, bn4 = (t & 15) * 8;
    int ge = m0 + arow;
    float acc[2][4][4];
#pragma unroll
    for (int a = 0; a < 2; a++)
#pragma unroll
        for (int b = 0; b < 4; b++)
#pragma unroll
            for (int c = 0; c < 4; c++) acc[a][b][c] = 0.f;

    float4 va = make_float4(0.f, 0.f, 0.f, 0.f);
    if (ge < E) va = *(const float4*)(ea + (size_t)ge * 64 + akq * 4);
    float4 vb0 = *(const float4*)(Wc + (size_t)bkr * 128 + bn4);
    float4 vb1 = *(const float4*)(Wc + (size_t)bkr * 128 + bn4 + 4);

    for (int k0 = 0; k0 < 64; k0 += 16) {
        *(float4*)&sA[arow * APAD + akq * 4] = va;
        *(float4*)&sB[bkr * BPAD + bn4]      = vb0;
        *(float4*)&sB[bkr * BPAD + bn4 + 4]  = vb1;
        __syncthreads();
        int kn = k0 + 16;
        if (kn < 64) {
            va = make_float4(0.f, 0.f, 0.f, 0.f);
            if (ge < E) va = *(const float4*)(ea + (size_t)ge * 64 + kn + akq * 4);
            vb0 = *(const float4*)(Wc + (size_t)(kn + bkr) * 128 + bn4);
            vb1 = *(const float4*)(Wc + (size_t)(kn + bkr) * 128 + bn4 + 4);
        }
        MMA_SLAB(sA, sB, acc)
        __syncthreads();
    }

    // single staging pass: every warp writes its (row,col) patch; one sync
#pragma unroll
    for (int mt = 0; mt < 2; mt++)
#pragma unroll
        for (int nt = 0; nt < 4; nt++)
#pragma unroll
            for (int half = 0; half < 2; half++) {
                int el = wm + mt * 16 + g + half * 8;   // 0..63
                int c = wn + nt * 8 + 2 * tg;
                stage[el * SPAD + c]     = acc[mt][nt][half * 2 + 0];
                stage[el * SPAD + c + 1] = acc[mt][nt][half * 2 + 1];
            }
    __syncthreads();

    // scatter: each warp handles 8 independent edges (deep MLP)
    {
        int j = lane * 4;
        float4 scv = *(const float4*)&sc[j];
        float4 shv = *(const float4*)&sh[j];
        float4 w0 = *(const float4*)&w1d[j];
        float4 w1v = *(const float4*)&w1d[128 + j];
        float4 w2 = *(const float4*)&w1d[256 + j];
#pragma unroll
        for (int i = 0; i < 8; i++) {
            int el = w * 8 + i;                 // 0..63
            int eg = m0 + el;
            if (eg < E) {
                int d = sdst[el], s2 = ssrc[el];
                float rp0 = srp[el * 3 + 0];
                float rp1 = srp[el * 3 + 1];
                float rp2 = srp[el * 3 + 2];
                float4 cv = *(const float4*)&stage[el * SPAD + j];
                float4 av = *(const float4*)&g_Ab[(size_t)d * 128 + j];
                float4 bv = *(const float4*)&g_Bb[(size_t)s2 * 128 + j];
                float m0v = cv.x + av.x + bv.x + rp0 * w0.x + rp1 * w1v.x + rp2 * w2.x;
                float m1v = cv.y + av.y + bv.y + rp0 * w0.y + rp1 * w1v.y + rp2 * w2.y;
                float m2v = cv.z + av.z + bv.z + rp0 * w0.z + rp1 * w1v.z + rp2 * w2.z;
                float m3v = cv.w + av.w + bv.w + rp0 * w0.w + rp1 * w1v.w + rp2 * w2.w;
                float r0 = fmaxf(fmaf(m0v, scv.x, shv.x), 0.f);
                float r1 = fmaxf(fmaf(m1v, scv.y, shv.y), 0.f);
                float r2 = fmaxf(fmaf(m2v, scv.z, shv.z), 0.f);
                float r3 = fmaxf(fmaf(m3v, scv.w, shv.w), 0.f);
                float* pS = &g_S[(size_t)d * 128 + j];
                asm volatile("red.global.add.v4.f32 [%0], {%1, %2, %3, %4};"
                             :: "l"(pS), "f"(r0), "f"(r1), "f"(r2), "f"(r3) : "memory");
            }
        }
    }
}

// ------- node update: h += relu( U + (S + selfmsg)@W2 + deg*b2 ) ---------------
__global__ __launch_bounds__(256, 3) void node1(
    const float* __restrict__ W2, const float* __restrict__ b2,
    const float* __restrict__ gn, const float* __restrict__ be,
    const float* __restrict__ b1, int M)
{
    __shared__ __align__(16) float sA[64 * APAD];
    __shared__ __align__(16) float sB[16 * BPAD];
    __shared__ float sc[128], sh[128], b2s[128];
    int t = threadIdx.x, lane = t & 31, w = t >> 5;
    if (t < 128) {
        float s = gn[t] * rsqrtf(1.0f + EPSBN);
        sc[t] = s;
        sh[t] = fmaf(b1[t], s, be[t]);
        b2s[t] = b2[t];
    }
    __syncthreads();
    int wm = (w & 1) * 32, wn = (w >> 1) * 32;
    int g = lane >> 2, tg = lane & 3;
    int m0 = blockIdx.x * 64;
    int arow = t >> 2, akq = t & 3;
    int bkr = t >> 4, bn4 = (t & 15) * 8;
    int gm = m0 + arow;
    float acc[2][4][4];
#pragma unroll
    for (int a = 0; a < 2; a++)
#pragma unroll
        for (int b = 0; b < 4; b++)
#pragma unroll
            for (int c = 0; c < 4; c++) acc[a][b][c] = 0.f;

    // prefetch raw vectors for k0=0
    float4 pv_s = make_float4(0.f, 0.f, 0.f, 0.f);
    float4 pv_a = pv_s, pv_b = pv_s;
    if (gm < M) {
        pv_s = *(const float4*)(g_S  + (size_t)gm * 128 + akq * 4);
        pv_a = *(const float4*)(g_Ab + (size_t)gm * 128 + akq * 4);
        pv_b = *(const float4*)(g_Bb + (size_t)gm * 128 + akq * 4);
    }
    float4 vb0 = *(const float4*)(W2 + (size_t)bkr * 128 + bn4);
    float4 vb1 = *(const float4*)(W2 + (size_t)bkr * 128 + bn4 + 4);

    for (int k0 = 0; k0 < 128; k0 += 16) {
        // build A values: S + relu(bn(A+B)) (self-loop message)
        {
            float out[4];
            float* sp = (float*)&pv_s; float* ap = (float*)&pv_a; float* bp = (float*)&pv_b;
#pragma unroll
            for (int j = 0; j < 4; j++) {
                int k = k0 + akq * 4 + j;
                float r = fmaxf(fmaf(ap[j] + bp[j], sc[k], sh[k]), 0.f);
                out[j] = sp[j] + r;
            }
            *(float4*)&sA[arow * APAD + akq * 4] = *(float4*)out;
        }
        *(float4*)&sB[bkr * BPAD + bn4]     = vb0;
        *(float4*)&sB[bkr * BPAD + bn4 + 4] = vb1;
        __syncthreads();
        int kn = k0 + 16;
        if (kn < 128) {
            pv_s = make_float4(0.f, 0.f, 0.f, 0.f);
            pv_a = pv_s; pv_b = pv_s;
            if (gm < M) {
                pv_s = *(const float4*)(g_S  + (size_t)gm * 128 + kn + akq * 4);
                pv_a = *(const float4*)(g_Ab + (size_t)gm * 128 + kn + akq * 4);
                pv_b = *(const float4*)(g_Bb + (size_t)gm * 128 + kn + akq * 4);
            }
            vb0 = *(const float4*)(W2 + (size_t)(kn + bkr) * 128 + bn4);
            vb1 = *(const float4*)(W2 + (size_t)(kn + bkr) * 128 + bn4 + 4);
        }
        MMA_SLAB(sA, sB, acc)
        __syncthreads();
    }
#pragma unroll
    for (int mt = 0; mt < 2; mt++) {
        int r0 = m0 + wm + mt * 16 + g;
#pragma unroll
        for (int nt = 0; nt < 4; nt++) {
            int c = wn + nt * 8 + 2 * tg;
#pragma unroll
            for (int half = 0; half < 2; half++) {
                int rr = r0 + half * 8;
                if (rr < M) {
                    float dg = g_deg[rr];
                    float u0 = g_U[(size_t)rr * 128 + c];
                    float u1 = g_U[(size_t)rr * 128 + c + 1];
                    float v0 = acc[mt][nt][half * 2 + 0] + u0 + dg * b2s[c];
                    float v1 = acc[mt][nt][half * 2 + 1] + u1 + dg * b2s[c + 1];
                    g_h[(size_t)rr * 128 + c]     += fmaxf(v0, 0.f);
                    g_h[(size_t)rr * 128 + c + 1] += fmaxf(v1, 0.f);
                }
            }
        }
    }
}

// ---------------- pooling + output MLP ------------------------------------------
__global__ void pool_kernel(int N) {
    int w = (blockIdx.x * blockDim.x + threadIdx.x) >> 5;
    int lane = threadIdx.x & 31;
    if (w >= N) return;
    int gph = g_batch[w];
    int j = lane * 4;
    float4 v = *(const float4*)&g_h[(size_t)w * 128 + j];
    float* p = &g_P[(size_t)gph * 128 + j];
    asm volatile("red.global.add.v4.f32 [%0], {%1, %2, %3, %4};"
                 :: "l"(p), "f"(v.x), "f"(v.y), "f"(v.z), "f"(v.w) : "memory");
    if (lane == 0) atomicAdd(&g_cnt[gph], 1.0f);
}

__global__ void head_kernel(
    const float* __restrict__ W1, const float* __restrict__ b1,
    const float* __restrict__ gn, const float* __restrict__ be,
    const float* __restrict__ W2, const float* __restrict__ b2,
    float* __restrict__ out)
{
    __shared__ float pl[128], o1[128];
    int gph = blockIdx.x;
    int t = threadIdx.x;
    float c = fmaxf(g_cnt[gph], 1.0f);
    pl[t] = g_P[gph * 128 + t] / c;
    __syncthreads();
    float acc = b1[t];
    for (int k = 0; k < 128; k++) acc = fmaf(pl[k], W1[k * 128 + t], acc);
    float s = gn[t] * rsqrtf(1.0f + EPSBN);
    o1[t] = fmaxf(fmaf(acc, s, be[t]), 0.f);
    __syncthreads();
    float acc2 = b2[t];
    for (int k = 0; k < 128; k++) acc2 = fmaf(o1[k], W2[k * 128 + t], acc2);
    out[gph * 128 + t] = acc2;
}

// ---------------- launch ---------------------------------------------------------
extern "C" void kernel_launch(void* const* d_in, const int* in_sizes, int n_in,
                              void* d_out, int out_size)
{
    const float* x       = (const float*)d_in[0];
    const void*  ei      = d_in[1];
    const float* ea      = (const float*)d_in[2];
    const float* pos     = (const float*)d_in[3];
    const void*  bt      = d_in[4];
    const float* Wi      = (const float*)d_in[5];
    const float* bi      = (const float*)d_in[6];
    const float* node_W  = (const float*)d_in[7];
    const float* node_b  = (const float*)d_in[8];
    const float* msg_W1  = (const float*)d_in[9];
    const float* msg_b1  = (const float*)d_in[10];
    const float* msg_g   = (const float*)d_in[11];
    const float* msg_be  = (const float*)d_in[12];
    const float* msg_W2  = (const float*)d_in[13];
    const float* msg_b2  = (const float*)d_in[14];
    const float* out_W1  = (const float*)d_in[15];
    const float* out_b1  = (const float*)d_in[16];
    const float* out_g   = (const float*)d_in[17];
    const float* out_be  = (const float*)d_in[18];
    const float* out_W2  = (const float*)d_in[19];
    const float* out_b2  = (const float*)d_in[20];

    int N = in_sizes[3] / 3;   // pos [N,3]
    int E = in_sizes[1] / 2;   // edge_index [2,E]

    void *hp, *Sp, *Pp, *cp;
    cudaGetSymbolAddress(&hp, g_h);
    cudaGetSymbolAddress(&Sp, g_S);
    cudaGetSymbolAddress(&Pp, g_P);
    cudaGetSymbolAddress(&cp, g_cnt);

    detect_kernel<<<1, 256>>>(ei, bt, N, E);
    int mx = (N > E ? N : E);
    convert_kernel<<<(mx + 255) / 256, 256>>>(ei, bt, N, E);
    deg_kernel<<<(E + 255) / 256, 256>>>(E);

    int nT = (N + 63) / 64;
    int eT = (E + 63) / 64;

    // h = x @ Wi + bi
    gemm64<<<nT, 256>>>(x, 256, Wi, bi, (float*)hp, N, 256);

    for (int l = 0; l < 3; l++) {
        const float* W1l = msg_W1 + (size_t)l * 323 * 128;
        // A = h@W1a, B = h@W1b, U = h@nodeW + node_b (one fused launch)
        gemm_h3<<<dim3(nT, 3), 256>>>(W1l, W1l + 128 * 128,
                                      node_W + (size_t)l * 128 * 128,
                                      node_b + l * 128, N);
        cudaMemsetAsync(Sp, 0, (size_t)N * 128 * sizeof(float));
        edge_fused<<<eT, 256>>>(ea, pos, W1l,
                                msg_g + l * 128, msg_be + l * 128,
                                msg_b1 + l * 128, E);
        node1<<<nT, 256>>>(msg_W2 + (size_t)l * 128 * 128, msg_b2 + l * 128,
                           msg_g + l * 128, msg_be + l * 128,
                           msg_b1 + l * 128, N);
    }

    cudaMemsetAsync(Pp, 0, GG * 128 * sizeof(float));
    cudaMemsetAsync(cp, 0, GG * sizeof(float));
    pool_kernel<<<(N * 32 + 255) / 256, 256>>>(N);
    head_kernel<<<GG, 128>>>(out_W1, out_b1, out_g, out_be, out_W2, out_b2,
                             (float*)d_out);
}

// round 15
// speedup vs baseline: 1.5995x; 1.4286x over previous
#include <cuda_runtime.h>
#include <math.h>

#define NN 50000
#define EE 400000
#define GG 64
#define EPSBN 1e-5f
#define AP2 12     // A tile row stride (uint32 bf16x2 pairs): banks (12g+tg)%32 all distinct
#define BP2 136    // B tile row stride (uint32): banks (8tg+g)%32 all distinct
#define SPAD 132   // staging tile row stride (floats)

// ---------------- scratch ------------------------------------------------------
__device__ float g_h[NN * 128];
__device__ float g_Ab[NN * 128];
__device__ float g_Bb[NN * 128];
__device__ float g_U[NN * 128];
__device__ float g_S[NN * 128];
__device__ int   g_src[EE];
__device__ int   g_dst[EE];
__device__ int   g_batch[NN];
__device__ float g_deg[NN];
__device__ float g_P[GG * 128];
__device__ float g_cnt[GG];
__device__ int   g_e64;
__device__ int   g_b64;

// ---------------- dtype detection ----------------------------------------------
__global__ void detect_kernel(const void* ei, const void* bt, int N, int E) {
    __shared__ int s_e, s_b;
    int t = threadIdx.x;
    if (t == 0) { s_e = 1; s_b = 1; }
    __syncthreads();
    const long long* p = (const long long*)ei;
    long long v = p[t];
    if (v < 0 || v >= (long long)N) s_e = 0;
    int base = N / 2 - 256; if (base < 0) base = 0;
    const long long* q = (const long long*)bt;
    long long w = q[base + t];
    if (w < 0 || w >= (long long)GG) s_b = 0;
    __syncthreads();
    if (t == 0) { g_e64 = s_e; g_b64 = s_b; }
}

__global__ void convert_kernel(const void* ei, const void* bt, int N, int E) {
    int i = blockIdx.x * blockDim.x + threadIdx.x;
    int e64 = g_e64, b64 = g_b64;
    if (i < E) {
        if (e64) {
            const long long* p = (const long long*)ei;
            g_src[i] = (int)p[i];
            g_dst[i] = (int)p[E + i];
        } else {
            const int* p = (const int*)ei;
            g_src[i] = p[i];
            g_dst[i] = p[E + i];
        }
    }
    if (i < N) {
        if (b64) g_batch[i] = (int)((const long long*)bt)[i];
        else     g_batch[i] = ((const int*)bt)[i];
        g_deg[i] = 1.0f;   // self loop
    }
}

__global__ void deg_kernel(int E) {
    int i = blockIdx.x * blockDim.x + threadIdx.x;
    if (i < E) atomicAdd(&g_deg[g_dst[i]], 1.0f);
}

// ---------------- bf16 split helpers --------------------------------------------
// pack {lo-half: bf16(x0), hi-half: bf16(x1)}; residual packed the same way.
__device__ __forceinline__ void bf16_split2(float x0, float x1,
                                            unsigned& hi, unsigned& lo) {
    asm("cvt.rn.bf16x2.f32 %0, %1, %2;" : "=r"(hi) : "f"(x1), "f"(x0));
    float h0 = __uint_as_float(hi << 16);
    float h1 = __uint_as_float(hi & 0xffff0000u);
    asm("cvt.rn.bf16x2.f32 %0, %1, %2;" : "=r"(lo) : "f"(x1 - h1), "f"(x0 - h0));
}

#define MMA_BF16(d, a, b)                                                  \
    asm volatile("mma.sync.aligned.m16n8k16.row.col.f32.bf16.bf16.f32 "    \
        "{%0,%1,%2,%3}, {%4,%5,%6,%7}, {%8,%9}, {%0,%1,%2,%3};"            \
        : "+f"((d)[0]), "+f"((d)[1]), "+f"((d)[2]), "+f"((d)[3])           \
        : "r"((a)[0]), "r"((a)[1]), "r"((a)[2]), "r"((a)[3]),              \
          "r"((b)[0]), "r"((b)[1]))

// k16 slab: direct packed-bf16x2 fragment loads + 3-term split MMA, M64xN128
#define MMA_SLAB(sAhi, sAlo, sBhi, sBlo, acc) {                                 \
    unsigned ahi[2][4], alo[2][4], bhi[4][2], blo[4][2];                        \
    _Pragma("unroll")                                                           \
    for (int mt = 0; mt < 2; mt++) {                                            \
        int base = (wm + mt * 16 + g) * AP2 + tg;                               \
        ahi[mt][0] = (sAhi)[base];             ahi[mt][1] = (sAhi)[base + 8 * AP2]; \
        ahi[mt][2] = (sAhi)[base + 4];         ahi[mt][3] = (sAhi)[base + 8 * AP2 + 4]; \
        alo[mt][0] = (sAlo)[base];             alo[mt][1] = (sAlo)[base + 8 * AP2]; \
        alo[mt][2] = (sAlo)[base + 4];         alo[mt][3] = (sAlo)[base + 8 * AP2 + 4]; \
    }                                                                           \
    _Pragma("unroll")                                                           \
    for (int nt = 0; nt < 4; nt++) {                                            \
        int n = wn + nt * 8 + g;                                                \
        bhi[nt][0] = (sBhi)[tg * BP2 + n]; bhi[nt][1] = (sBhi)[(tg + 4) * BP2 + n]; \
        blo[nt][0] = (sBlo)[tg * BP2 + n]; blo[nt][1] = (sBlo)[(tg + 4) * BP2 + n]; \
    }                                                                           \
    _Pragma("unroll")                                                           \
    for (int mt = 0; mt < 2; mt++)                                              \
        _Pragma("unroll")                                                       \
        for (int nt = 0; nt < 4; nt++) {                                        \
            MMA_BF16(acc[mt][nt], ahi[mt], bhi[nt]);                            \
            MMA_BF16(acc[mt][nt], ahi[mt], blo[nt]);                            \
            MMA_BF16(acc[mt][nt], alo[mt], bhi[nt]);                            \
        } }

// store helpers: A float4 (4 consecutive k) -> 2 packed pairs in hi/lo tiles
#define STORE_A_BF16(sAhi, sAlo, va) {                                          \
    unsigned h0, l0, h1, l1;                                                    \
    bf16_split2((va).x, (va).y, h0, l0);                                        \
    bf16_split2((va).z, (va).w, h1, l1);                                        \
    *(uint2*)&(sAhi)[arow * AP2 + akq * 2] = make_uint2(h0, h1);                \
    *(uint2*)&(sAlo)[arow * AP2 + akq * 2] = make_uint2(l0, l1); }

// B: two row-float4s (rows 2bp, 2bp+1, cols bc..bc+3) -> 4 packed cols
#define STORE_B_BF16(sBhi, sBlo, w0, w1) {                                      \
    unsigned bh0, bl0, bh1, bl1, bh2, bl2, bh3, bl3;                            \
    bf16_split2((w0).x, (w1).x, bh0, bl0);                                      \
    bf16_split2((w0).y, (w1).y, bh1, bl1);                                      \
    bf16_split2((w0).z, (w1).z, bh2, bl2);                                      \
    bf16_split2((w0).w, (w1).w, bh3, bl3);                                      \
    *(uint4*)&(sBhi)[bp * BP2 + bc] = make_uint4(bh0, bh1, bh2, bh3);           \
    *(uint4*)&(sBlo)[bp * BP2 + bc] = make_uint4(bl0, bl1, bl2, bl3); }

// ---------------- generic GEMM (init): C[M,128] = A[M,K]@W + bias, M-tile 64 ---
__global__ __launch_bounds__(256) void gemm64(
    const float* __restrict__ Ap, int lda,
    const float* __restrict__ Wp, const float* __restrict__ bias,
    float* __restrict__ Cp, int M, int K)
{
    __shared__ __align__(16) unsigned sAhi[64 * AP2], sAlo[64 * AP2];
    __shared__ __align__(16) unsigned sBhi[8 * BP2], sBlo[8 * BP2];
    int t = threadIdx.x, lane = t & 31, w = t >> 5;
    int wm = (w & 1) * 32, wn = (w >> 1) * 32;
    int g = lane >> 2, tg = lane & 3;
    int m0 = blockIdx.x * 64;
    int arow = t >> 2, akq = t & 3;
    int bp = t >> 5, bc = (t & 31) * 4;
    int gm = m0 + arow;
    float acc[2][4][4];
#pragma unroll
    for (int a = 0; a < 2; a++)
#pragma unroll
        for (int b = 0; b < 4; b++)
#pragma unroll
            for (int c = 0; c < 4; c++) acc[a][b][c] = 0.f;

    float4 va = make_float4(0.f, 0.f, 0.f, 0.f);
    if (gm < M) va = *(const float4*)(Ap + (size_t)gm * lda + akq * 4);
    float4 w0 = *(const float4*)(Wp + (size_t)(2 * bp) * 128 + bc);
    float4 w1 = *(const float4*)(Wp + (size_t)(2 * bp + 1) * 128 + bc);

    for (int k0 = 0; k0 < K; k0 += 16) {
        STORE_A_BF16(sAhi, sAlo, va)
        STORE_B_BF16(sBhi, sBlo, w0, w1)
        __syncthreads();
        int kn = k0 + 16;
        if (kn < K) {
            va = make_float4(0.f, 0.f, 0.f, 0.f);
            if (gm < M) va = *(const float4*)(Ap + (size_t)gm * lda + kn + akq * 4);
            w0 = *(const float4*)(Wp + (size_t)(kn + 2 * bp) * 128 + bc);
            w1 = *(const float4*)(Wp + (size_t)(kn + 2 * bp + 1) * 128 + bc);
        }
        MMA_SLAB(sAhi, sAlo, sBhi, sBlo, acc)
        __syncthreads();
    }
#pragma unroll
    for (int mt = 0; mt < 2; mt++) {
        int r0 = m0 + wm + mt * 16 + g;
#pragma unroll
        for (int nt = 0; nt < 4; nt++) {
            int c = wn + nt * 8 + 2 * tg;
            float b0 = bias ? bias[c] : 0.f;
            float b1 = bias ? bias[c + 1] : 0.f;
            if (r0 < M) {
                Cp[(size_t)r0 * 128 + c]     = acc[mt][nt][0] + b0;
                Cp[(size_t)r0 * 128 + c + 1] = acc[mt][nt][1] + b1;
            }
            if (r0 + 8 < M) {
                Cp[(size_t)(r0 + 8) * 128 + c]     = acc[mt][nt][2] + b0;
                Cp[(size_t)(r0 + 8) * 128 + c + 1] = acc[mt][nt][3] + b1;
            }
        }
    }
}

// ------- fused node GEMMs: y=0: A=h@W1a, y=1: B=h@W1b, y=2: U=h@nodeW+node_b ---
__global__ __launch_bounds__(256) void gemm_h3(
    const float* __restrict__ Wa, const float* __restrict__ Wb,
    const float* __restrict__ Wn, const float* __restrict__ nodeB, int M)
{
    __shared__ __align__(16) unsigned sAhi[64 * AP2], sAlo[64 * AP2];
    __shared__ __align__(16) unsigned sBhi[8 * BP2], sBlo[8 * BP2];
    int y = blockIdx.y;
    const float* Wp = (y == 0) ? Wa : ((y == 1) ? Wb : Wn);
    float* Cp = (y == 0) ? g_Ab : ((y == 1) ? g_Bb : g_U);
    const float* bias = (y == 2) ? nodeB : 0;

    int t = threadIdx.x, lane = t & 31, w = t >> 5;
    int wm = (w & 1) * 32, wn = (w >> 1) * 32;
    int g = lane >> 2, tg = lane & 3;
    int m0 = blockIdx.x * 64;
    int arow = t >> 2, akq = t & 3;
    int bp = t >> 5, bc = (t & 31) * 4;
    int gm = m0 + arow;
    float acc[2][4][4];
#pragma unroll
    for (int a = 0; a < 2; a++)
#pragma unroll
        for (int b = 0; b < 4; b++)
#pragma unroll
            for (int c = 0; c < 4; c++) acc[a][b][c] = 0.f;

    float4 va = make_float4(0.f, 0.f, 0.f, 0.f);
    if (gm < M) va = *(const float4*)(g_h + (size_t)gm * 128 + akq * 4);
    float4 w0 = *(const float4*)(Wp + (size_t)(2 * bp) * 128 + bc);
    float4 w1 = *(const float4*)(Wp + (size_t)(2 * bp + 1) * 128 + bc);

    for (int k0 = 0; k0 < 128; k0 += 16) {
        STORE_A_BF16(sAhi, sAlo, va)
        STORE_B_BF16(sBhi, sBlo, w0, w1)
        __syncthreads();
        int kn = k0 + 16;
        if (kn < 128) {
            va = make_float4(0.f, 0.f, 0.f, 0.f);
            if (gm < M) va = *(const float4*)(g_h + (size_t)gm * 128 + kn + akq * 4);
            w0 = *(const float4*)(Wp + (size_t)(kn + 2 * bp) * 128 + bc);
            w1 = *(const float4*)(Wp + (size_t)(kn + 2 * bp + 1) * 128 + bc);
        }
        MMA_SLAB(sAhi, sAlo, sBhi, sBlo, acc)
        __syncthreads();
    }
#pragma unroll
    for (int mt = 0; mt < 2; mt++) {
        int r0 = m0 + wm + mt * 16 + g;
#pragma unroll
        for (int nt = 0; nt < 4; nt++) {
            int c = wn + nt * 8 + 2 * tg;
            float b0 = bias ? bias[c] : 0.f;
            float b1 = bias ? bias[c + 1] : 0.f;
            if (r0 < M) {
                Cp[(size_t)r0 * 128 + c]     = acc[mt][nt][0] + b0;
                Cp[(size_t)r0 * 128 + c + 1] = acc[mt][nt][1] + b1;
            }
            if (r0 + 8 < M) {
                Cp[(size_t)(r0 + 8) * 128 + c]     = acc[mt][nt][2] + b0;
                Cp[(size_t)(r0 + 8) * 128 + c + 1] = acc[mt][nt][3] + b1;
            }
        }
    }
}

// ------- fused edge pass: GEMM(ea@W1c) + gather A/B/relpos + BN/ReLU + scatter --
__global__ __launch_bounds__(256) void edge_fused(
    const float* __restrict__ ea, const float* __restrict__ pos,
    const float* __restrict__ W1,
    const float* __restrict__ gn, const float* __restrict__ be,
    const float* __restrict__ b1, int E)
{
    __shared__ __align__(16) unsigned sAhi[64 * AP2], sAlo[64 * AP2];
    __shared__ __align__(16) unsigned sBhi[8 * BP2], sBlo[8 * BP2];
    __shared__ __align__(16) float stage[64 * SPAD];
    __shared__ __align__(16) float w1d[3 * 128];
    __shared__ __align__(16) float sc[128], sh[128];
    __shared__ float srp[64 * 3];
    __shared__ int   sdst[64], ssrc[64];

    int t = threadIdx.x, lane = t & 31, w = t >> 5;
    int wm = (w & 1) * 32, wn = (w >> 1) * 32;
    int g = lane >> 2, tg = lane & 3;
    int m0 = blockIdx.x * 64;

    if (t < 128) {
        float s = gn[t] * rsqrtf(1.0f + EPSBN);
        sc[t] = s;
        sh[t] = fmaf(b1[t], s, be[t]);
        w1d[t]       = W1[320 * 128 + t];
        w1d[128 + t] = W1[321 * 128 + t];
        w1d[256 + t] = W1[322 * 128 + t];
    }
    if (t < 64) {
        int e = m0 + t;
        int s = 0, d = 0;
        float r0 = 0.f, r1 = 0.f, r2 = 0.f;
        if (e < E) {
            s = g_src[e]; d = g_dst[e];
            r0 = pos[d * 3 + 0] - pos[s * 3 + 0];
            r1 = pos[d * 3 + 1] - pos[s * 3 + 1];
            r2 = pos[d * 3 + 2] - pos[s * 3 + 2];
        }
        ssrc[t] = s; sdst[t] = d;
        srp[t * 3 + 0] = r0; srp[t * 3 + 1] = r1; srp[t * 3 + 2] = r2;
    }

    const float* Wc = W1 + 256 * 128;
    int arow = t >> 2, akq = t & 3;
    int bp = t >> 5, bc = (t & 31) * 4;
    int ge = m0 + arow;
    float acc[2][4][4];
#pragma unroll
    for (int a = 0; a < 2; a++)
#pragma unroll
        for (int b = 0; b < 4; b++)
#pragma unroll
            for (int c = 0; c < 4; c++) acc[a][b][c] = 0.f;

    float4 va = make_float4(0.f, 0.f, 0.f, 0.f);
    if (ge < E) va = *(const float4*)(ea + (size_t)ge * 64 + akq * 4);
    float4 w0 = *(const float4*)(Wc + (size_t)(2 * bp) * 128 + bc);
    float4 w1 = *(const float4*)(Wc + (size_t)(2 * bp + 1) * 128 + bc);

    for (int k0 = 0; k0 < 64; k0 += 16) {
        STORE_A_BF16(sAhi, sAlo, va)
        STORE_B_BF16(sBhi, sBlo, w0, w1)
        __syncthreads();
        int kn = k0 + 16;
        if (kn < 64) {
            va = make_float4(0.f, 0.f, 0.f, 0.f);
            if (ge < E) va = *(const float4*)(ea + (size_t)ge * 64 + kn + akq * 4);
            w0 = *(const float4*)(Wc + (size_t)(kn + 2 * bp) * 128 + bc);
            w1 = *(const float4*)(Wc + (size_t)(kn + 2 * bp + 1) * 128 + bc);
        }
        MMA_SLAB(sAhi, sAlo, sBhi, sBlo, acc)
        __syncthreads();
    }

    // single staging pass: every warp writes its (row,col) patch; one sync
#pragma unroll
    for (int mt = 0; mt < 2; mt++)
#pragma unroll
        for (int nt = 0; nt < 4; nt++)
#pragma unroll
            for (int half = 0; half < 2; half++) {
                int el = wm + mt * 16 + g + half * 8;   // 0..63
                int c = wn + nt * 8 + 2 * tg;
                stage[el * SPAD + c]     = acc[mt][nt][half * 2 + 0];
                stage[el * SPAD + c + 1] = acc[mt][nt][half * 2 + 1];
            }
    __syncthreads();

    // scatter: each warp handles 8 independent edges (deep MLP)
    {
        int j = lane * 4;
        float4 scv = *(const float4*)&sc[j];
        float4 shv = *(const float4*)&sh[j];
        float4 w0v = *(const float4*)&w1d[j];
        float4 w1v = *(const float4*)&w1d[128 + j];
        float4 w2v = *(const float4*)&w1d[256 + j];
#pragma unroll
        for (int i = 0; i < 8; i++) {
            int el = w * 8 + i;                 // 0..63
            int eg = m0 + el;
            if (eg < E) {
                int d = sdst[el], s2 = ssrc[el];
                float rp0 = srp[el * 3 + 0];
                float rp1 = srp[el * 3 + 1];
                float rp2 = srp[el * 3 + 2];
                float4 cv = *(const float4*)&stage[el * SPAD + j];
                float4 av = *(const float4*)&g_Ab[(size_t)d * 128 + j];
                float4 bv = *(const float4*)&g_Bb[(size_t)s2 * 128 + j];
                float m0v = cv.x + av.x + bv.x + rp0 * w0v.x + rp1 * w1v.x + rp2 * w2v.x;
                float m1v = cv.y + av.y + bv.y + rp0 * w0v.y + rp1 * w1v.y + rp2 * w2v.y;
                float m2v = cv.z + av.z + bv.z + rp0 * w0v.z + rp1 * w1v.z + rp2 * w2v.z;
                float m3v = cv.w + av.w + bv.w + rp0 * w0v.w + rp1 * w1v.w + rp2 * w2v.w;
                float r0 = fmaxf(fmaf(m0v, scv.x, shv.x), 0.f);
                float r1 = fmaxf(fmaf(m1v, scv.y, shv.y), 0.f);
                float r2 = fmaxf(fmaf(m2v, scv.z, shv.z), 0.f);
                float r3 = fmaxf(fmaf(m3v, scv.w, shv.w), 0.f);
                float* pS = &g_S[(size_t)d * 128 + j];
                asm volatile("red.global.add.v4.f32 [%0], {%1, %2, %3, %4};"
                             :: "l"(pS), "f"(r0), "f"(r1), "f"(r2), "f"(r3) : "memory");
            }
        }
    }
}

// ------- node update: h += relu( U + (S + selfmsg)@W2 + deg*b2 ) ---------------
__global__ __launch_bounds__(256) void node1(
    const float* __restrict__ W2, const float* __restrict__ b2,
    const float* __restrict__ gn, const float* __restrict__ be,
    const float* __restrict__ b1, int M)
{
    __shared__ __align__(16) unsigned sAhi[64 * AP2], sAlo[64 * AP2];
    __shared__ __align__(16) unsigned sBhi[8 * BP2], sBlo[8 * BP2];
    __shared__ float sc[128], sh[128], b2s[128];
    int t = threadIdx.x, lane = t & 31, w = t >> 5;
    if (t < 128) {
        float s = gn[t] * rsqrtf(1.0f + EPSBN);
        sc[t] = s;
        sh[t] = fmaf(b1[t], s, be[t]);
        b2s[t] = b2[t];
    }
    __syncthreads();
    int wm = (w & 1) * 32, wn = (w >> 1) * 32;
    int g = lane >> 2, tg = lane & 3;
    int m0 = blockIdx.x * 64;
    int arow = t >> 2, akq = t & 3;
    int bp = t >> 5, bc = (t & 31) * 4;
    int gm = m0 + arow;
    float acc[2][4][4];
#pragma unroll
    for (int a = 0; a < 2; a++)
#pragma unroll
        for (int b = 0; b < 4; b++)
#pragma unroll
            for (int c = 0; c < 4; c++) acc[a][b][c] = 0.f;

    // prefetch raw vectors for k0=0
    float4 pv_s = make_float4(0.f, 0.f, 0.f, 0.f);
    float4 pv_a = pv_s, pv_b = pv_s;
    if (gm < M) {
        pv_s = *(const float4*)(g_S  + (size_t)gm * 128 + akq * 4);
        pv_a = *(const float4*)(g_Ab + (size_t)gm * 128 + akq * 4);
        pv_b = *(const float4*)(g_Bb + (size_t)gm * 128 + akq * 4);
    }
    float4 w0 = *(const float4*)(W2 + (size_t)(2 * bp) * 128 + bc);
    float4 w1 = *(const float4*)(W2 + (size_t)(2 * bp + 1) * 128 + bc);

    for (int k0 = 0; k0 < 128; k0 += 16) {
        // build A values: S + relu(bn(A+B)) (self-loop message), pack bf16
        {
            float out[4];
            float* sp = (float*)&pv_s; float* ap = (float*)&pv_a; float* bpv = (float*)&pv_b;
#pragma unroll
            for (int j = 0; j < 4; j++) {
                int k = k0 + akq * 4 + j;
                float r = fmaxf(fmaf(ap[j] + bpv[j], sc[k], sh[k]), 0.f);
                out[j] = sp[j] + r;
            }
            unsigned h0, l0, h1, l1;
            bf16_split2(out[0], out[1], h0, l0);
            bf16_split2(out[2], out[3], h1, l1);
            *(uint2*)&sAhi[arow * AP2 + akq * 2] = make_uint2(h0, h1);
            *(uint2*)&sAlo[arow * AP2 + akq * 2] = make_uint2(l0, l1);
        }
        STORE_B_BF16(sBhi, sBlo, w0, w1)
        __syncthreads();
        int kn = k0 + 16;
        if (kn < 128) {
            pv_s = make_float4(0.f, 0.f, 0.f, 0.f);
            pv_a = pv_s; pv_b = pv_s;
            if (gm < M) {
                pv_s = *(const float4*)(g_S  + (size_t)gm * 128 + kn + akq * 4);
                pv_a = *(const float4*)(g_Ab + (size_t)gm * 128 + kn + akq * 4);
                pv_b = *(const float4*)(g_Bb + (size_t)gm * 128 + kn + akq * 4);
            }
            w0 = *(const float4*)(W2 + (size_t)(kn + 2 * bp) * 128 + bc);
            w1 = *(const float4*)(W2 + (size_t)(kn + 2 * bp + 1) * 128 + bc);
        }
        MMA_SLAB(sAhi, sAlo, sBhi, sBlo, acc)
        __syncthreads();
    }
#pragma unroll
    for (int mt = 0; mt < 2; mt++) {
        int r0 = m0 + wm + mt * 16 + g;
#pragma unroll
        for (int nt = 0; nt < 4; nt++) {
            int c = wn + nt * 8 + 2 * tg;
#pragma unroll
            for (int half = 0; half < 2; half++) {
                int rr = r0 + half * 8;
                if (rr < M) {
                    float dg = g_deg[rr];
                    float u0 = g_U[(size_t)rr * 128 + c];
                    float u1 = g_U[(size_t)rr * 128 + c + 1];
                    float v0 = acc[mt][nt][half * 2 + 0] + u0 + dg * b2s[c];
                    float v1 = acc[mt][nt][half * 2 + 1] + u1 + dg * b2s[c + 1];
                    g_h[(size_t)rr * 128 + c]     += fmaxf(v0, 0.f);
                    g_h[(size_t)rr * 128 + c + 1] += fmaxf(v1, 0.f);
                }
            }
        }
    }
}

// ---------------- pooling + output MLP ------------------------------------------
__global__ void pool_kernel(int N) {
    int w = (blockIdx.x * blockDim.x + threadIdx.x) >> 5;
    int lane = threadIdx.x & 31;
    if (w >= N) return;
    int gph = g_batch[w];
    int j = lane * 4;
    float4 v = *(const float4*)&g_h[(size_t)w * 128 + j];
    float* p = &g_P[(size_t)gph * 128 + j];
    asm volatile("red.global.add.v4.f32 [%0], {%1, %2, %3, %4};"
                 :: "l"(p), "f"(v.x), "f"(v.y), "f"(v.z), "f"(v.w) : "memory");
    if (lane == 0) atomicAdd(&g_cnt[gph], 1.0f);
}

__global__ void head_kernel(
    const float* __restrict__ W1, const float* __restrict__ b1,
    const float* __restrict__ gn, const float* __restrict__ be,
    const float* __restrict__ W2, const float* __restrict__ b2,
    float* __restrict__ out)
{
    __shared__ float pl[128], o1[128];
    int gph = blockIdx.x;
    int t = threadIdx.x;
    float c = fmaxf(g_cnt[gph], 1.0f);
    pl[t] = g_P[gph * 128 + t] / c;
    __syncthreads();
    float acc = b1[t];
    for (int k = 0; k < 128; k++) acc = fmaf(pl[k], W1[k * 128 + t], acc);
    float s = gn[t] * rsqrtf(1.0f + EPSBN);
    o1[t] = fmaxf(fmaf(acc, s, be[t]), 0.f);
    __syncthreads();
    float acc2 = b2[t];
    for (int k = 0; k < 128; k++) acc2 = fmaf(o1[k], W2[k * 128 + t], acc2);
    out[gph * 128 + t] = acc2;
}

// ---------------- launch ---------------------------------------------------------
extern "C" void kernel_launch(void* const* d_in, const int* in_sizes, int n_in,
                              void* d_out, int out_size)
{
    const float* x       = (const float*)d_in[0];
    const void*  ei      = d_in[1];
    const float* ea      = (const float*)d_in[2];
    const float* pos     = (const float*)d_in[3];
    const void*  bt      = d_in[4];
    const float* Wi      = (const float*)d_in[5];
    const float* bi      = (const float*)d_in[6];
    const float* node_W  = (const float*)d_in[7];
    const float* node_b  = (const float*)d_in[8];
    const float* msg_W1  = (const float*)d_in[9];
    const float* msg_b1  = (const float*)d_in[10];
    const float* msg_g   = (const float*)d_in[11];
    const float* msg_be  = (const float*)d_in[12];
    const float* msg_W2  = (const float*)d_in[13];
    const float* msg_b2  = (const float*)d_in[14];
    const float* out_W1  = (const float*)d_in[15];
    const float* out_b1  = (const float*)d_in[16];
    const float* out_g   = (const float*)d_in[17];
    const float* out_be  = (const float*)d_in[18];
    const float* out_W2  = (const float*)d_in[19];
    const float* out_b2  = (const float*)d_in[20];

    int N = in_sizes[3] / 3;   // pos [N,3]
    int E = in_sizes[1] / 2;   // edge_index [2,E]

    void *hp, *Sp, *Pp, *cp;
    cudaGetSymbolAddress(&hp, g_h);
    cudaGetSymbolAddress(&Sp, g_S);
    cudaGetSymbolAddress(&Pp, g_P);
    cudaGetSymbolAddress(&cp, g_cnt);

    detect_kernel<<<1, 256>>>(ei, bt, N, E);
    int mx = (N > E ? N : E);
    convert_kernel<<<(mx + 255) / 256, 256>>>(ei, bt, N, E);
    deg_kernel<<<(E + 255) / 256, 256>>>(E);

    int nT = (N + 63) / 64;
    int eT = (E + 63) / 64;

    // h = x @ Wi + bi
    gemm64<<<nT, 256>>>(x, 256, Wi, bi, (float*)hp, N, 256);

    for (int l = 0; l < 3; l++) {
        const float* W1l = msg_W1 + (size_t)l * 323 * 128;
        // A = h@W1a, B = h@W1b, U = h@nodeW + node_b (one fused launch)
        gemm_h3<<<dim3(nT, 3), 256>>>(W1l, W1l + 128 * 128,
                                      node_W + (size_t)l * 128 * 128,
                                      node_b + l * 128, N);
        cudaMemsetAsync(Sp, 0, (size_t)N * 128 * sizeof(float));
        edge_fused<<<eT, 256>>>(ea, pos, W1l,
                                msg_g + l * 128, msg_be + l * 128,
                                msg_b1 + l * 128, E);
        node1<<<nT, 256>>>(msg_W2 + (size_t)l * 128 * 128, msg_b2 + l * 128,
                           msg_g + l * 128, msg_be + l * 128,
                           msg_b1 + l * 128, N);
    }

    cudaMemsetAsync(Pp, 0, GG * 128 * sizeof(float));
    cudaMemsetAsync(cp, 0, GG * sizeof(float));
    pool_kernel<<<(N * 32 + 255) / 256, 256>>>(N);
    head_kernel<<<GG, 128>>>(out_W1, out_b1, out_g, out_be, out_W2, out_b2,
                             (float*)d_out);
}